// round 12
// baseline (speedup 1.0000x reference)
#include <cuda_runtime.h>
#include <cuda_fp16.h>
#include <math.h>
#include <stdint.h>

typedef __half fp16;

#define Dc   1024
#define Ec   8
#define Fc   4096
#define NTOK 8192
#define NSLOT (NTOK * 2)
#define PADR 128
#define MAX_TILES 136
#define BM 128
#define BN 128
#define BK 32
#define NTHR 512

// smem stage: 2 tiles (A, B), 128 rows x 80B (32 fp16 = 64B data + 16B pad)
#define ROWB 80
#define ST_A 0
#define ST_B (128 * ROWB)
#define STAGE (2 * 128 * ROWB)      // 20480 B
#define NSTG 4
#define SMEM_DYN (NSTG * STAGE)     // 81920 B

// ---------------- scratch (device globals) ---------------------------------
__device__ __align__(1024) fp16  g_xg [(size_t)NTOK * Dc];            // token-order fp16 x
__device__ __align__(1024) fp16  g_h  [(size_t)(NSLOT + PADR) * Fc];  // slot-order hidden
__device__ __align__(1024) float g_y  [(size_t)NSLOT * Dc];           // slot-order GEMM2 out
__device__ __align__(1024) fp16  g_W1t[(size_t)Ec * Fc * Dc];         // [e][f][d]
__device__ __align__(1024) fp16  g_W2t[(size_t)Ec * Dc * Fc];         // [e][d][f]
__device__ int   g_perm[NSLOT];
__device__ int   g_tok_slot[NTOK * 2];
__device__ int   g_tok_e[NTOK * 2];
__device__ float g_tok_w[NTOK * 2];
__device__ int   g_tile_base[MAX_TILES];
__device__ int   g_tile_expert[MAX_TILES];
__device__ int   g_tile_rows[MAX_TILES];
__device__ int   g_ntiles;

// ---------------- helpers ----------------------------------------------------
__device__ __forceinline__ uint32_t smem_u32(const void* p) {
    uint32_t a;
    asm("{ .reg .u64 t; cvta.to.shared.u64 t, %1; cvt.u32.u64 %0, t; }" : "=r"(a) : "l"(p));
    return a;
}
__device__ __forceinline__ void cp16(uint32_t s, const void* g) {
    asm volatile("cp.async.cg.shared.global [%0], [%1], 16;" :: "r"(s), "l"(g));
}
__device__ __forceinline__ void cp_commit() { asm volatile("cp.async.commit_group;" ::: "memory"); }
#define CP_WAIT(n) asm volatile("cp.async.wait_group %0;" :: "n"(n) : "memory")

__device__ __forceinline__ void ldmx4(uint32_t addr, uint32_t r[4]) {
    asm volatile("ldmatrix.sync.aligned.m8n8.x4.shared.b16 {%0,%1,%2,%3}, [%4];"
        : "=r"(r[0]), "=r"(r[1]), "=r"(r[2]), "=r"(r[3]) : "r"(addr));
}
__device__ __forceinline__ void mma16816(float c[4], const uint32_t a[4], const uint32_t* b) {
    asm volatile("mma.sync.aligned.m16n8k16.row.col.f32.f16.f16.f32 "
        "{%0,%1,%2,%3}, {%4,%5,%6,%7}, {%8,%9}, {%0,%1,%2,%3};"
        : "+f"(c[0]), "+f"(c[1]), "+f"(c[2]), "+f"(c[3])
        : "r"(a[0]), "r"(a[1]), "r"(a[2]), "r"(a[3]), "r"(b[0]), "r"(b[1]));
}
__device__ __forceinline__ float gelu_exact(float v) {
    return 0.5f * v * (1.0f + erff(v * 0.70710678118654752f));
}
__device__ __forceinline__ uint32_t pack2(fp16 a, fp16 b) {
    return (uint32_t)__half_as_ushort(a) | ((uint32_t)__half_as_ushort(b) << 16);
}

// ---------------- gate (fp32 routing + fused x -> fp16 conversion) -----------
__global__ void k_gate(const float* __restrict__ x, const float* __restrict__ Wg,
                       const float* __restrict__ bg) {
    int gtid = blockIdx.x * blockDim.x + threadIdx.x;
    int tok = gtid >> 5, lane = gtid & 31;
    if (tok >= NTOK) return;
    const float* xr = x + (size_t)tok * Dc;
    float acc[Ec];
#pragma unroll
    for (int e = 0; e < Ec; e++) acc[e] = 0.0f;
    for (int d = lane; d < Dc; d += 32) {
        float xv = xr[d];
        const float4* wr = (const float4*)(Wg + (size_t)d * Ec);
        float4 w0 = wr[0], w1 = wr[1];
        acc[0] += xv * w0.x; acc[1] += xv * w0.y; acc[2] += xv * w0.z; acc[3] += xv * w0.w;
        acc[4] += xv * w1.x; acc[5] += xv * w1.y; acc[6] += xv * w1.z; acc[7] += xv * w1.w;
    }
#pragma unroll
    for (int e = 0; e < Ec; e++)
#pragma unroll
        for (int off = 16; off > 0; off >>= 1)
            acc[e] += __shfl_down_sync(0xFFFFFFFFu, acc[e], off);
    if (lane == 0) {
        float v[Ec];
#pragma unroll
        for (int e = 0; e < Ec; e++) v[e] = acc[e] + bg[e];
        int b0 = 0;
#pragma unroll
        for (int e = 1; e < Ec; e++) if (v[e] > v[b0]) b0 = e;
        int b1 = -1; float s = -1e30f;
#pragma unroll
        for (int e = 0; e < Ec; e++) { if (e == b0) continue; if (v[e] > s) { s = v[e]; b1 = e; } }
        float ed = expf(s - v[b0]);
        float p0 = 1.0f / (1.0f + ed);
        float p1 = ed * p0;
        g_tok_e[tok * 2 + 0] = b0; g_tok_e[tok * 2 + 1] = b1;
        g_tok_w[tok * 2 + 0] = p0; g_tok_w[tok * 2 + 1] = p1;
    }
    fp16* orow = g_xg + (size_t)tok * Dc;
    for (int d = lane * 2; d < Dc; d += 64) {
        float2 v = *(const float2*)(xr + d);
        *(uint32_t*)(orow + d) = pack2(__float2half_rn(v.x), __float2half_rn(v.y));
    }
}

// ---------------- scatter: single block builds counts, tiles, perm -----------
__global__ void k_scatter() {
    __shared__ int cnt[Ec], cur[Ec];
    int tid = threadIdx.x;
    if (tid < Ec) cnt[tid] = 0;
    __syncthreads();
    for (int t = tid; t < NTOK; t += 1024) {
        atomicAdd(&cnt[g_tok_e[2 * t]], 1);
        atomicAdd(&cnt[g_tok_e[2 * t + 1]], 1);
    }
    __syncthreads();
    if (tid == 0) {
        int o = 0, nt = 0;
        for (int e = 0; e < Ec; e++) {
            int c = cnt[e];
            cur[e] = o;
            for (int s = 0; s < c; s += BM) {
                g_tile_base[nt] = o + s; g_tile_expert[nt] = e;
                g_tile_rows[nt] = min(BM, c - s); nt++;
            }
            o += c;
        }
        g_ntiles = nt;
    }
    __syncthreads();
    for (int t = tid; t < NTOK; t += 1024) {
#pragma unroll
        for (int k = 0; k < 2; k++) {
            int e = g_tok_e[2 * t + k];
            int pos = atomicAdd(&cur[e], 1);
            g_perm[pos] = t;
            g_tok_slot[2 * t + k] = pos;
        }
    }
}

// ---------------- weight transpose: in [e][R][C] fp32 -> out [e][C][R] fp16 --
__global__ void k_tsplit(const float* __restrict__ in, int which, int R, int C) {
    fp16* o = which ? g_W2t : g_W1t;
    __shared__ float t[32][33];
    int e = blockIdx.z;
    int r0 = blockIdx.y * 32, c0 = blockIdx.x * 32;
    int tx = threadIdx.x, ty = threadIdx.y;
    const float* base = in + (size_t)e * R * C;
#pragma unroll
    for (int i = 0; i < 4; i++)
        t[ty + 8 * i][tx] = base[(size_t)(r0 + ty + 8 * i) * C + c0 + tx];
    __syncthreads();
    size_t ob = (size_t)e * C * R;
#pragma unroll
    for (int i = 0; i < 4; i++) {
        float v = t[tx][ty + 8 * i];
        o[ob + (size_t)(c0 + ty + 8 * i) * R + r0 + tx] = __float2half_rn(v);
    }
}

// ---------------- GEMM core: CTA 128x128x32, 512 thr, 16 warps 4Mx4N ---------
// warp tile 32x32, acc 32 regs/thread -> 2 CTAs/SM = 32 warps/SM.
// Each thread owns ONE smem row segment pair (32B) of either A or B.
__device__ __forceinline__ void gemm_core(uint32_t sm0,
        const fp16* __restrict__ src, uint32_t sdst, int NC, int tid,
        float (&acc)[2][4][4]) {
    const int lane = tid & 31, wid = tid >> 5;
    const int wm = (wid & 3) * 32, wn = (wid >> 2) * 32;

    const uint32_t a_off = (uint32_t)(wm + (lane & 15)) * ROWB + ((lane & 16) ? 16u : 0u);
    const uint32_t b_off = (uint32_t)(wn + (lane & 7) + ((lane & 16) >> 1)) * ROWB
                           + ((lane & 8) ? 16u : 0u);

#pragma unroll
    for (int mt = 0; mt < 2; mt++)
#pragma unroll
        for (int nt = 0; nt < 4; nt++)
#pragma unroll
            for (int q = 0; q < 4; q++) acc[mt][nt][q] = 0.0f;

    // prologue: 3 stages in flight (each thread: 2 x cp16 = 32B contiguous)
#pragma unroll
    for (int s = 0; s < 3; s++) {
        uint32_t sb = sm0 + (uint32_t)s * STAGE;
        const fp16* g = src + s * BK;
        cp16(sb + sdst, g);
        cp16(sb + sdst + 16, g + 8);
        cp_commit();
    }

    for (int k = 0; k < NC; k++) {
        int rem = NC - 1 - k;
        if (rem >= 2)      { CP_WAIT(2); }
        else if (rem == 1) { CP_WAIT(1); }
        else               { CP_WAIT(0); }
        __syncthreads();
        if (k + 3 < NC) {
            uint32_t sb = sm0 + (uint32_t)((k + 3) & (NSTG - 1)) * STAGE;
            const fp16* g = src + (k + 3) * BK;
            cp16(sb + sdst, g);
            cp16(sb + sdst + 16, g + 8);
            cp_commit();
        }
        uint32_t sb = sm0 + (uint32_t)(k & (NSTG - 1)) * STAGE;
#pragma unroll
        for (int kk = 0; kk < 2; kk++) {
            const uint32_t kb = kk * 32;
            uint32_t ah[2][4], bh[2][4];
#pragma unroll
            for (int mt = 0; mt < 2; mt++)
                ldmx4(sb + ST_A + a_off + mt * 16 * ROWB + kb, ah[mt]);
#pragma unroll
            for (int p = 0; p < 2; p++)
                ldmx4(sb + ST_B + b_off + p * 16 * ROWB + kb, bh[p]);
#pragma unroll
            for (int p = 0; p < 2; p++)
#pragma unroll
                for (int q = 0; q < 2; q++)
#pragma unroll
                    for (int mt = 0; mt < 2; mt++)
                        mma16816(acc[mt][p * 2 + q], ah[mt], &bh[p][q * 2]);
        }
        __syncthreads();
    }
}

// ---------------- GEMM1: h[slot] = fp16(gelu(x[perm] @ W1t^T + b1)) ----------
__global__ void __launch_bounds__(NTHR, 2)
k_mma1(const float* __restrict__ b1) {
    int t = blockIdx.y;
    if (t >= g_ntiles) return;
    const int n0 = blockIdx.x * BN;
    const int base = g_tile_base[t], e = g_tile_expert[t], rows = g_tile_rows[t];

    extern __shared__ char dsm[];
    uint32_t sm0 = smem_u32(dsm);
    int tid = threadIdx.x;

    // per-thread load role: tid<256 -> A rows (perm-gathered), else B rows
    int row  = (tid & 255) >> 1;
    int cpos = (tid & 1) * 2;
    const fp16* src;
    uint32_t sdst;
    if (tid < 256) {
        int pidx = min(base + row, NSLOT - 1);
        src  = g_xg + (size_t)g_perm[pidx] * Dc + cpos * 8;
        sdst = ST_A + (uint32_t)row * ROWB + cpos * 16;
    } else {
        src  = g_W1t + ((size_t)e * Fc + n0 + row) * Dc + cpos * 8;
        sdst = ST_B + (uint32_t)row * ROWB + cpos * 16;
    }

    float acc[2][4][4];
    gemm_core(sm0, src, sdst, Dc / BK, tid, acc);

    const int lane = tid & 31, wid = tid >> 5;
    const int wm = (wid & 3) * 32, wn = (wid >> 2) * 32;
    const int rb = wm + (lane >> 2);
    const int cb = wn + (lane & 3) * 2;
    const float* b1e = b1 + (size_t)e * Fc + n0;
    float bv[4][2];
#pragma unroll
    for (int nt = 0; nt < 4; nt++) {
        bv[nt][0] = b1e[cb + nt * 8];
        bv[nt][1] = b1e[cb + nt * 8 + 1];
    }
#pragma unroll
    for (int mt = 0; mt < 2; mt++)
#pragma unroll
        for (int half = 0; half < 2; half++) {
            int r = rb + mt * 16 + half * 8;
            if (r >= rows) continue;
            size_t ro = (size_t)(base + r) * Fc + n0;
#pragma unroll
            for (int nt = 0; nt < 4; nt++) {
                float v0 = gelu_exact(acc[mt][nt][half * 2 + 0] + bv[nt][0]);
                float v1 = gelu_exact(acc[mt][nt][half * 2 + 1] + bv[nt][1]);
                *(uint32_t*)(g_h + ro + cb + nt * 8) =
                    pack2(__float2half_rn(v0), __float2half_rn(v1));
            }
        }
}

// ---------------- GEMM2: y[slot] = h @ W2t^T + b2 (plain stores) --------------
__global__ void __launch_bounds__(NTHR, 2)
k_mma2(const float* __restrict__ b2) {
    int t = blockIdx.y;
    if (t >= g_ntiles) return;
    const int n0 = blockIdx.x * BN;
    const int base = g_tile_base[t], e = g_tile_expert[t], rows = g_tile_rows[t];

    extern __shared__ char dsm[];
    uint32_t sm0 = smem_u32(dsm);
    int tid = threadIdx.x;

    int row  = (tid & 255) >> 1;
    int cpos = (tid & 1) * 2;
    const fp16* src;
    uint32_t sdst;
    if (tid < 256) {
        src  = g_h + (size_t)(base + row) * Fc + cpos * 8;   // padded region allocated
        sdst = ST_A + (uint32_t)row * ROWB + cpos * 16;
    } else {
        src  = g_W2t + ((size_t)e * Dc + n0 + row) * Fc + cpos * 8;
        sdst = ST_B + (uint32_t)row * ROWB + cpos * 16;
    }

    float acc[2][4][4];
    gemm_core(sm0, src, sdst, Fc / BK, tid, acc);

    const int lane = tid & 31, wid = tid >> 5;
    const int wm = (wid & 3) * 32, wn = (wid >> 2) * 32;
    const int rb = wm + (lane >> 2);
    const int cb = wn + (lane & 3) * 2;
    const float* b2e = b2 + (size_t)e * Dc + n0;
    float bv[4][2];
#pragma unroll
    for (int nt = 0; nt < 4; nt++) {
        bv[nt][0] = b2e[cb + nt * 8];
        bv[nt][1] = b2e[cb + nt * 8 + 1];
    }
#pragma unroll
    for (int mt = 0; mt < 2; mt++)
#pragma unroll
        for (int half = 0; half < 2; half++) {
            int r = rb + mt * 16 + half * 8;
            if (r >= rows) continue;
            float* yrow = g_y + (size_t)(base + r) * Dc + n0;
#pragma unroll
            for (int nt = 0; nt < 4; nt++) {
                int c = cb + nt * 8;
                float2 v;
                v.x = acc[mt][nt][half * 2 + 0] + bv[nt][0];
                v.y = acc[mt][nt][half * 2 + 1] + bv[nt][1];
                *(float2*)(yrow + c) = v;
            }
        }
}

// ---------------- combine: out[t] = w0*y[s0] + w1*y[s1] -----------------------
__global__ void k_combine(float* __restrict__ out) {
    int t = blockIdx.x;
    int tid = threadIdx.x;
    int s0 = g_tok_slot[t * 2 + 0], s1 = g_tok_slot[t * 2 + 1];
    float w0 = g_tok_w[t * 2 + 0],  w1 = g_tok_w[t * 2 + 1];
    const float4* y0 = (const float4*)(g_y + (size_t)s0 * Dc);
    const float4* y1 = (const float4*)(g_y + (size_t)s1 * Dc);
    float4* o = (float4*)(out + (size_t)t * Dc);
    float4 a = y0[tid], b = y1[tid];
    float4 r;
    r.x = w0 * a.x + w1 * b.x;
    r.y = w0 * a.y + w1 * b.y;
    r.z = w0 * a.z + w1 * b.z;
    r.w = w0 * a.w + w1 * b.w;
    o[tid] = r;
}

// ---------------- launch (stream fork-join; mma1 = 4th submitted launch) ------
extern "C" void kernel_launch(void* const* d_in, const int* in_sizes, int n_in,
                              void* d_out, int out_size) {
    const float* x  = (const float*)d_in[0];
    const float* Wg = (const float*)d_in[1];
    const float* bg = (const float*)d_in[2];
    const float* W1 = (const float*)d_in[3];
    const float* b1 = (const float*)d_in[4];
    const float* W2 = (const float*)d_in[5];
    const float* b2 = (const float*)d_in[6];
    float* out = (float*)d_out;

    static cudaStream_t s1 = nullptr, s2 = nullptr;
    static cudaEvent_t e_root = nullptr, e_w1 = nullptr, e_w2 = nullptr;
    static int configured = 0;
    if (!configured) {
        cudaFuncSetAttribute(k_mma1, cudaFuncAttributeMaxDynamicSharedMemorySize, SMEM_DYN);
        cudaFuncSetAttribute(k_mma2, cudaFuncAttributeMaxDynamicSharedMemorySize, SMEM_DYN);
        cudaStreamCreateWithFlags(&s1, cudaStreamNonBlocking);
        cudaStreamCreateWithFlags(&s2, cudaStreamNonBlocking);
        cudaEventCreateWithFlags(&e_root, cudaEventDisableTiming);
        cudaEventCreateWithFlags(&e_w1, cudaEventDisableTiming);
        cudaEventCreateWithFlags(&e_w2, cudaEventDisableTiming);
        configured = 1;
    }

    cudaEventRecord(e_root, 0);
    cudaStreamWaitEvent(s1, e_root, 0);
    cudaStreamWaitEvent(s2, e_root, 0);

    k_gate<<<NTOK / 8, 256>>>(x, Wg, bg);                                        // 0
    k_scatter<<<1, 1024>>>();                                                    // 1
    k_tsplit<<<dim3(Fc / 32, Dc / 32, Ec), dim3(32, 8), 0, s1>>>(W1, 0, Dc, Fc); // 2
    cudaEventRecord(e_w1, s1);
    cudaStreamWaitEvent(0, e_w1, 0);
    k_mma1<<<dim3(Fc / BN, MAX_TILES), NTHR, SMEM_DYN>>>(b1);                    // 3 -> global 5 (ncu)
    k_tsplit<<<dim3(Dc / 32, Fc / 32, Ec), dim3(32, 8), 0, s2>>>(W2, 1, Fc, Dc); // 4
    cudaEventRecord(e_w2, s2);
    cudaStreamWaitEvent(0, e_w2, 0);
    k_mma2<<<dim3(Dc / BN, MAX_TILES), NTHR, SMEM_DYN>>>(b2);                    // 5
    k_combine<<<NTOK, 256>>>(out);                                               // 6
}

// round 13
// speedup vs baseline: 1.0542x; 1.0542x over previous
#include <cuda_runtime.h>
#include <cuda_fp16.h>
#include <math.h>
#include <stdint.h>

typedef __half fp16;

#define Dc   1024
#define Ec   8
#define Fc   4096
#define NTOK 8192
#define NSLOT (NTOK * 2)
#define PADR 128
#define MAX_TILES 136
#define BM 128
#define BN 128
#define BK 32

// smem stage: 2 tiles (A, B), 128 rows x 80B (32 fp16 = 64B data + 16B pad)
#define ROWB 80
#define ST_A 0
#define ST_B (128 * ROWB)
#define STAGE (2 * 128 * ROWB)      // 20480 B
#define NSTG 4
#define SMEM_DYN (NSTG * STAGE)     // 81920 B

// ---------------- scratch (device globals) ---------------------------------
__device__ __align__(1024) fp16  g_xg [(size_t)(NSLOT + PADR) * Dc];  // slot-order fp16 x
__device__ __align__(1024) fp16  g_h  [(size_t)(NSLOT + PADR) * Fc];  // slot-order hidden
__device__ __align__(1024) float g_y  [(size_t)NSLOT * Dc];           // slot-order GEMM2 out
__device__ __align__(1024) fp16  g_W1t[(size_t)Ec * Fc * Dc];         // [e][f][d]
__device__ __align__(1024) fp16  g_W2t[(size_t)Ec * Dc * Fc];         // [e][d][f]
__device__ int   g_perm[NSLOT];
__device__ int   g_tok_slot[NTOK * 2];   // token -> its 2 slots
__device__ int   g_tok_e[NTOK * 2];
__device__ float g_tok_w[NTOK * 2];
__device__ int   g_tile_base[MAX_TILES];
__device__ int   g_tile_expert[MAX_TILES];
__device__ int   g_tile_rows[MAX_TILES];
__device__ int   g_ntiles;

// ---------------- helpers ----------------------------------------------------
__device__ __forceinline__ uint32_t smem_u32(const void* p) {
    uint32_t a;
    asm("{ .reg .u64 t; cvta.to.shared.u64 t, %1; cvt.u32.u64 %0, t; }" : "=r"(a) : "l"(p));
    return a;
}
__device__ __forceinline__ void cp16(uint32_t s, const void* g) {
    asm volatile("cp.async.cg.shared.global [%0], [%1], 16;" :: "r"(s), "l"(g));
}
__device__ __forceinline__ void cp_commit() { asm volatile("cp.async.commit_group;" ::: "memory"); }
#define CP_WAIT(n) asm volatile("cp.async.wait_group %0;" :: "n"(n) : "memory")

__device__ __forceinline__ void ldmx4(uint32_t addr, uint32_t r[4]) {
    asm volatile("ldmatrix.sync.aligned.m8n8.x4.shared.b16 {%0,%1,%2,%3}, [%4];"
        : "=r"(r[0]), "=r"(r[1]), "=r"(r[2]), "=r"(r[3]) : "r"(addr));
}
__device__ __forceinline__ void mma16816(float c[4], const uint32_t a[4], const uint32_t* b) {
    asm volatile("mma.sync.aligned.m16n8k16.row.col.f32.f16.f16.f32 "
        "{%0,%1,%2,%3}, {%4,%5,%6,%7}, {%8,%9}, {%0,%1,%2,%3};"
        : "+f"(c[0]), "+f"(c[1]), "+f"(c[2]), "+f"(c[3])
        : "r"(a[0]), "r"(a[1]), "r"(a[2]), "r"(a[3]), "r"(b[0]), "r"(b[1]));
}
__device__ __forceinline__ float gelu_exact(float v) {
    return 0.5f * v * (1.0f + erff(v * 0.70710678118654752f));
}
__device__ __forceinline__ uint32_t pack2(fp16 a, fp16 b) {
    return (uint32_t)__half_as_ushort(a) | ((uint32_t)__half_as_ushort(b) << 16);
}

// ---------------- gate (fp32, exact routing) ---------------------------------
__global__ void k_gate(const float* __restrict__ x, const float* __restrict__ Wg,
                       const float* __restrict__ bg) {
    int gtid = blockIdx.x * blockDim.x + threadIdx.x;
    int tok = gtid >> 5, lane = gtid & 31;
    if (tok >= NTOK) return;
    const float* xr = x + (size_t)tok * Dc;
    float acc[Ec];
#pragma unroll
    for (int e = 0; e < Ec; e++) acc[e] = 0.0f;
    for (int d = lane; d < Dc; d += 32) {
        float xv = xr[d];
        const float4* wr = (const float4*)(Wg + (size_t)d * Ec);
        float4 w0 = wr[0], w1 = wr[1];
        acc[0] += xv * w0.x; acc[1] += xv * w0.y; acc[2] += xv * w0.z; acc[3] += xv * w0.w;
        acc[4] += xv * w1.x; acc[5] += xv * w1.y; acc[6] += xv * w1.z; acc[7] += xv * w1.w;
    }
#pragma unroll
    for (int e = 0; e < Ec; e++)
#pragma unroll
        for (int off = 16; off > 0; off >>= 1)
            acc[e] += __shfl_down_sync(0xFFFFFFFFu, acc[e], off);
    if (lane == 0) {
        float v[Ec];
#pragma unroll
        for (int e = 0; e < Ec; e++) v[e] = acc[e] + bg[e];
        int b0 = 0;
#pragma unroll
        for (int e = 1; e < Ec; e++) if (v[e] > v[b0]) b0 = e;
        int b1 = -1; float s = -1e30f;
#pragma unroll
        for (int e = 0; e < Ec; e++) { if (e == b0) continue; if (v[e] > s) { s = v[e]; b1 = e; } }
        float ed = expf(s - v[b0]);
        float p0 = 1.0f / (1.0f + ed);
        float p1 = ed * p0;
        g_tok_e[tok * 2 + 0] = b0; g_tok_e[tok * 2 + 1] = b1;
        g_tok_w[tok * 2 + 0] = p0; g_tok_w[tok * 2 + 1] = p1;
    }
}

// ---------------- scatter: single block builds counts, tiles, perm -----------
__global__ void k_scatter() {
    __shared__ int cnt[Ec], cur[Ec];
    int tid = threadIdx.x;
    if (tid < Ec) cnt[tid] = 0;
    __syncthreads();
    for (int t = tid; t < NTOK; t += 1024) {
        atomicAdd(&cnt[g_tok_e[2 * t]], 1);
        atomicAdd(&cnt[g_tok_e[2 * t + 1]], 1);
    }
    __syncthreads();
    if (tid == 0) {
        int o = 0, nt = 0;
        for (int e = 0; e < Ec; e++) {
            int c = cnt[e];
            cur[e] = o;
            for (int s = 0; s < c; s += BM) {
                g_tile_base[nt] = o + s; g_tile_expert[nt] = e;
                g_tile_rows[nt] = min(BM, c - s); nt++;
            }
            o += c;
        }
        g_ntiles = nt;
    }
    __syncthreads();
    for (int t = tid; t < NTOK; t += 1024) {
#pragma unroll
        for (int k = 0; k < 2; k++) {
            int e = g_tok_e[2 * t + k];
            int pos = atomicAdd(&cur[e], 1);
            g_perm[pos] = t;
            g_tok_slot[2 * t + k] = pos;
        }
    }
}

// ---------------- gather x rows -> slot-order fp16 (float4 loads) ------------
__global__ void k_gather(const float* __restrict__ x) {
    int s = blockIdx.x;
    int tid = threadIdx.x;
    if (s < NSLOT) {
        const float4* src = (const float4*)(x + (size_t)g_perm[s] * Dc);
        // Dc/4 = 256 float4 per row, 256 threads -> 1 each
        float4 v = __ldg(&src[tid]);
        uint32_t lo = pack2(__float2half_rn(v.x), __float2half_rn(v.y));
        uint32_t hi = pack2(__float2half_rn(v.z), __float2half_rn(v.w));
        uint2 o; o.x = lo; o.y = hi;
        *(uint2*)(g_xg + (size_t)s * Dc + tid * 4) = o;
    } else {
        uint2 z; z.x = 0u; z.y = 0u;
        *(uint2*)(g_xg + (size_t)s * Dc + tid * 4) = z;
    }
}

// ---------------- weight transpose: in [e][R][C] fp32 -> out [e][C][R] fp16 --
__global__ void k_tsplit(const float* __restrict__ in, int which, int R, int C) {
    fp16* o = which ? g_W2t : g_W1t;
    __shared__ float t[32][33];
    int e = blockIdx.z;
    int r0 = blockIdx.y * 32, c0 = blockIdx.x * 32;
    int tx = threadIdx.x, ty = threadIdx.y;
    const float* base = in + (size_t)e * R * C;
#pragma unroll
    for (int i = 0; i < 4; i++)
        t[ty + 8 * i][tx] = base[(size_t)(r0 + ty + 8 * i) * C + c0 + tx];
    __syncthreads();
    size_t ob = (size_t)e * C * R;
#pragma unroll
    for (int i = 0; i < 4; i++) {
        float v = t[tx][ty + 8 * i];
        o[ob + (size_t)(c0 + ty + 8 * i) * R + r0 + tx] = __float2half_rn(v);
    }
}

// ---------------- GEMM core (R7/R10 exact: proven best) -----------------------
// CTA 128x128x32, 8 warps in 4(M) x 2(N) grid, warp tile 32x64. 2 CTAs/SM.
__device__ __forceinline__ void load_stage(uint32_t sb,
        const fp16* __restrict__ A, const fp16* __restrict__ B,
        int ldk, int k0, int tid) {
#pragma unroll
    for (int i = 0; i < 2; i++) {
        int idx = tid * 2 + i;
        int row = idx >> 2, cpos = idx & 3;
        uint32_t so = (uint32_t)row * ROWB + cpos * 16;
        size_t go = (size_t)row * ldk + k0 + cpos * 8;
        cp16(sb + ST_A + so, A + go);
        cp16(sb + ST_B + so, B + go);
    }
}

__device__ __forceinline__ void gemm_core(uint32_t sm0,
        const fp16* __restrict__ A, const fp16* __restrict__ B,
        int ldk, int NC, int tid, float (&acc)[2][8][4]) {
    const int lane = tid & 31, wid = tid >> 5;
    const int wm = (wid & 3) * 32, wn = (wid >> 2) * 64;

    const uint32_t a_off = (uint32_t)(wm + (lane & 15)) * ROWB + ((lane & 16) ? 16u : 0u);
    const uint32_t b_off = (uint32_t)(wn + (lane & 7) + ((lane & 16) >> 1)) * ROWB
                           + ((lane & 8) ? 16u : 0u);

#pragma unroll
    for (int mt = 0; mt < 2; mt++)
#pragma unroll
        for (int nt = 0; nt < 8; nt++)
#pragma unroll
            for (int q = 0; q < 4; q++) acc[mt][nt][q] = 0.0f;

    // prologue: 3 stages in flight
#pragma unroll
    for (int s = 0; s < 3; s++) {
        load_stage(sm0 + (uint32_t)s * STAGE, A, B, ldk, s * BK, tid);
        cp_commit();
    }

    for (int k = 0; k < NC; k++) {
        int rem = NC - 1 - k;
        if (rem >= 2)      { CP_WAIT(2); }
        else if (rem == 1) { CP_WAIT(1); }
        else               { CP_WAIT(0); }
        __syncthreads();
        if (k + 3 < NC) {
            load_stage(sm0 + (uint32_t)((k + 3) & (NSTG - 1)) * STAGE, A, B,
                       ldk, (k + 3) * BK, tid);
            cp_commit();
        }
        uint32_t sb = sm0 + (uint32_t)(k & (NSTG - 1)) * STAGE;
#pragma unroll
        for (int kk = 0; kk < 2; kk++) {
            const uint32_t kb = kk * 32;
            uint32_t ah[2][4], bh[4][4];
#pragma unroll
            for (int mt = 0; mt < 2; mt++)
                ldmx4(sb + ST_A + a_off + mt * 16 * ROWB + kb, ah[mt]);
#pragma unroll
            for (int p = 0; p < 4; p++)
                ldmx4(sb + ST_B + b_off + p * 16 * ROWB + kb, bh[p]);
#pragma unroll
            for (int p = 0; p < 4; p++)
#pragma unroll
                for (int q = 0; q < 2; q++)
#pragma unroll
                    for (int mt = 0; mt < 2; mt++)
                        mma16816(acc[mt][p * 2 + q], ah[mt], &bh[p][q * 2]);
        }
        __syncthreads();
    }
}

// ---------------- GEMM1: h = fp16(gelu(xg @ W1t^T + b1)) ----------------------
__global__ void __launch_bounds__(256, 2)
k_mma1(const float* __restrict__ b1) {
    int t = blockIdx.y;
    if (t >= g_ntiles) return;
    const int n0 = blockIdx.x * BN;
    const int base = g_tile_base[t], e = g_tile_expert[t], rows = g_tile_rows[t];

    extern __shared__ char dsm[];
    uint32_t sm0 = smem_u32(dsm);
    int tid = threadIdx.x;

    float acc[2][8][4];
    gemm_core(sm0, g_xg + (size_t)base * Dc,
              g_W1t + ((size_t)e * Fc + n0) * Dc, Dc, Dc / BK, tid, acc);

    const int lane = tid & 31, wid = tid >> 5;
    const int wm = (wid & 3) * 32, wn = (wid >> 2) * 64;
    const int rb = wm + (lane >> 2);
    const int cb = wn + (lane & 3) * 2;
    const float* b1e = b1 + (size_t)e * Fc + n0;
    float bv[8][2];
#pragma unroll
    for (int nt = 0; nt < 8; nt++) {
        bv[nt][0] = b1e[cb + nt * 8];
        bv[nt][1] = b1e[cb + nt * 8 + 1];
    }
#pragma unroll
    for (int mt = 0; mt < 2; mt++)
#pragma unroll
        for (int half = 0; half < 2; half++) {
            int r = rb + mt * 16 + half * 8;
            if (r >= rows) continue;
            size_t ro = (size_t)(base + r) * Fc + n0;
#pragma unroll
            for (int nt = 0; nt < 8; nt++) {
                float v0 = gelu_exact(acc[mt][nt][half * 2 + 0] + bv[nt][0]);
                float v1 = gelu_exact(acc[mt][nt][half * 2 + 1] + bv[nt][1]);
                *(uint32_t*)(g_h + ro + cb + nt * 8) =
                    pack2(__float2half_rn(v0), __float2half_rn(v1));
            }
        }
}

// ---------------- GEMM2: y[slot] = h @ W2t^T + b2 (plain stores) --------------
__global__ void __launch_bounds__(256, 2)
k_mma2(const float* __restrict__ b2) {
    int t = blockIdx.y;
    if (t >= g_ntiles) return;
    const int n0 = blockIdx.x * BN;
    const int base = g_tile_base[t], e = g_tile_expert[t], rows = g_tile_rows[t];

    extern __shared__ char dsm[];
    uint32_t sm0 = smem_u32(dsm);
    int tid = threadIdx.x;

    float acc[2][8][4];
    gemm_core(sm0, g_h + (size_t)base * Fc,
              g_W2t + ((size_t)e * Dc + n0) * Fc, Fc, Fc / BK, tid, acc);

    const int lane = tid & 31, wid = tid >> 5;
    const int wm = (wid & 3) * 32, wn = (wid >> 2) * 64;
    const int rb = wm + (lane >> 2);
    const int cb = wn + (lane & 3) * 2;
    const float* b2e = b2 + (size_t)e * Dc + n0;
    float bv[8][2];
#pragma unroll
    for (int nt = 0; nt < 8; nt++) {
        bv[nt][0] = b2e[cb + nt * 8];
        bv[nt][1] = b2e[cb + nt * 8 + 1];
    }
#pragma unroll
    for (int mt = 0; mt < 2; mt++)
#pragma unroll
        for (int half = 0; half < 2; half++) {
            int r = rb + mt * 16 + half * 8;
            if (r >= rows) continue;
            float* yrow = g_y + (size_t)(base + r) * Dc + n0;
#pragma unroll
            for (int nt = 0; nt < 8; nt++) {
                int c = cb + nt * 8;
                float2 v;
                v.x = acc[mt][nt][half * 2 + 0] + bv[nt][0];
                v.y = acc[mt][nt][half * 2 + 1] + bv[nt][1];
                *(float2*)(yrow + c) = v;
            }
        }
}

// ---------------- combine: out[t] = w0*y[s0] + w1*y[s1] -----------------------
__global__ void k_combine(float* __restrict__ out) {
    int t = blockIdx.x;
    int tid = threadIdx.x;
    int s0 = g_tok_slot[t * 2 + 0], s1 = g_tok_slot[t * 2 + 1];
    float w0 = g_tok_w[t * 2 + 0],  w1 = g_tok_w[t * 2 + 1];
    const float4* y0 = (const float4*)(g_y + (size_t)s0 * Dc);
    const float4* y1 = (const float4*)(g_y + (size_t)s1 * Dc);
    float4* o = (float4*)(out + (size_t)t * Dc);
    float4 a = y0[tid], b = y1[tid];
    float4 r;
    r.x = w0 * a.x + w1 * b.x;
    r.y = w0 * a.y + w1 * b.y;
    r.z = w0 * a.z + w1 * b.z;
    r.w = w0 * a.w + w1 * b.w;
    o[tid] = r;
}

// ---------------- launch (R10 stream fork-join, fused scatter) -----------------
extern "C" void kernel_launch(void* const* d_in, const int* in_sizes, int n_in,
                              void* d_out, int out_size) {
    const float* x  = (const float*)d_in[0];
    const float* Wg = (const float*)d_in[1];
    const float* bg = (const float*)d_in[2];
    const float* W1 = (const float*)d_in[3];
    const float* b1 = (const float*)d_in[4];
    const float* W2 = (const float*)d_in[5];
    const float* b2 = (const float*)d_in[6];
    float* out = (float*)d_out;

    static cudaStream_t s1 = nullptr, s2 = nullptr;
    static cudaEvent_t e_root = nullptr, e_w1 = nullptr, e_w2 = nullptr;
    static int configured = 0;
    if (!configured) {
        cudaFuncSetAttribute(k_mma1, cudaFuncAttributeMaxDynamicSharedMemorySize, SMEM_DYN);
        cudaFuncSetAttribute(k_mma2, cudaFuncAttributeMaxDynamicSharedMemorySize, SMEM_DYN);
        cudaStreamCreateWithFlags(&s1, cudaStreamNonBlocking);
        cudaStreamCreateWithFlags(&s2, cudaStreamNonBlocking);
        cudaEventCreateWithFlags(&e_root, cudaEventDisableTiming);
        cudaEventCreateWithFlags(&e_w1, cudaEventDisableTiming);
        cudaEventCreateWithFlags(&e_w2, cudaEventDisableTiming);
        configured = 1;
    }

    // fork: weight conversions on side streams (start at t=0)
    cudaEventRecord(e_root, 0);
    cudaStreamWaitEvent(s1, e_root, 0);
    cudaStreamWaitEvent(s2, e_root, 0);
    k_tsplit<<<dim3(Fc / 32, Dc / 32, Ec), dim3(32, 8), 0, s1>>>(W1, 0, Dc, Fc);
    cudaEventRecord(e_w1, s1);
    k_tsplit<<<dim3(Dc / 32, Fc / 32, Ec), dim3(32, 8), 0, s2>>>(W2, 1, Fc, Dc);
    cudaEventRecord(e_w2, s2);

    // main stream: routing chain (overlaps W1/W2 conversion)
    k_gate<<<NTOK / 8, 256>>>(x, Wg, bg);
    k_scatter<<<1, 1024>>>();
    k_gather<<<NSLOT + PADR, 256>>>(x);

    // join W1 before GEMM1; W2 conversion keeps running under GEMM1
    cudaStreamWaitEvent(0, e_w1, 0);
    k_mma1<<<dim3(Fc / BN, MAX_TILES), 256, SMEM_DYN>>>(b1);

    // join W2 before GEMM2
    cudaStreamWaitEvent(0, e_w2, 0);
    k_mma2<<<dim3(Dc / BN, MAX_TILES), 256, SMEM_DYN>>>(b2);
    k_combine<<<NTOK, 256>>>(out);
}

// round 14
// speedup vs baseline: 1.0562x; 1.0018x over previous
#include <cuda_runtime.h>
#include <cuda_fp16.h>
#include <math.h>
#include <stdint.h>

typedef __half fp16;

#define Dc   1024
#define Ec   8
#define Fc   4096
#define NTOK 8192
#define NSLOT (NTOK * 2)
#define PADR 128
#define MAX_TILES 136
#define BM 128
#define BN 128
#define BK 32

// smem stage: 2 tiles (A, B), 128 rows x 80B (32 fp16 = 64B data + 16B pad)
#define ROWB 80
#define ST_A 0
#define ST_B (128 * ROWB)
#define STAGE (2 * 128 * ROWB)      // 20480 B
#define NSTG 5
#define SMEM_DYN (NSTG * STAGE)     // 102400 B ; x2 CTAs = 204.8 KB < 228 KB/SM

// ---------------- scratch (device globals) ---------------------------------
__device__ __align__(1024) fp16  g_xg [(size_t)(NSLOT + PADR) * Dc];  // slot-order fp16 x
__device__ __align__(1024) fp16  g_h  [(size_t)(NSLOT + PADR) * Fc];  // slot-order hidden
__device__ __align__(1024) fp16  g_y  [(size_t)NSLOT * Dc];           // slot-order GEMM2 out (fp16)
__device__ __align__(1024) fp16  g_W1t[(size_t)Ec * Fc * Dc];         // [e][f][d]
__device__ __align__(1024) fp16  g_W2t[(size_t)Ec * Dc * Fc];         // [e][d][f]
__device__ int   g_perm[NSLOT];
__device__ int   g_tok_slot[NTOK * 2];   // token -> its 2 slots
__device__ int   g_tok_e[NTOK * 2];
__device__ float g_tok_w[NTOK * 2];
__device__ int   g_tile_base[MAX_TILES];
__device__ int   g_tile_expert[MAX_TILES];
__device__ int   g_tile_rows[MAX_TILES];
__device__ int   g_ntiles;

// ---------------- helpers ----------------------------------------------------
__device__ __forceinline__ uint32_t smem_u32(const void* p) {
    uint32_t a;
    asm("{ .reg .u64 t; cvta.to.shared.u64 t, %1; cvt.u32.u64 %0, t; }" : "=r"(a) : "l"(p));
    return a;
}
__device__ __forceinline__ void cp16(uint32_t s, const void* g) {
    asm volatile("cp.async.cg.shared.global [%0], [%1], 16;" :: "r"(s), "l"(g));
}
__device__ __forceinline__ void cp_commit() { asm volatile("cp.async.commit_group;" ::: "memory"); }
#define CP_WAIT(n) asm volatile("cp.async.wait_group %0;" :: "n"(n) : "memory")

__device__ __forceinline__ void ldmx4(uint32_t addr, uint32_t r[4]) {
    asm volatile("ldmatrix.sync.aligned.m8n8.x4.shared.b16 {%0,%1,%2,%3}, [%4];"
        : "=r"(r[0]), "=r"(r[1]), "=r"(r[2]), "=r"(r[3]) : "r"(addr));
}
__device__ __forceinline__ void mma16816(float c[4], const uint32_t a[4], const uint32_t* b) {
    asm volatile("mma.sync.aligned.m16n8k16.row.col.f32.f16.f16.f32 "
        "{%0,%1,%2,%3}, {%4,%5,%6,%7}, {%8,%9}, {%0,%1,%2,%3};"
        : "+f"(c[0]), "+f"(c[1]), "+f"(c[2]), "+f"(c[3])
        : "r"(a[0]), "r"(a[1]), "r"(a[2]), "r"(a[3]), "r"(b[0]), "r"(b[1]));
}
__device__ __forceinline__ float gelu_exact(float v) {
    return 0.5f * v * (1.0f + erff(v * 0.70710678118654752f));
}
__device__ __forceinline__ uint32_t pack2(fp16 a, fp16 b) {
    return (uint32_t)__half_as_ushort(a) | ((uint32_t)__half_as_ushort(b) << 16);
}

// ---------------- gate (fp32, exact routing) ---------------------------------
__global__ void k_gate(const float* __restrict__ x, const float* __restrict__ Wg,
                       const float* __restrict__ bg) {
    int gtid = blockIdx.x * blockDim.x + threadIdx.x;
    int tok = gtid >> 5, lane = gtid & 31;
    if (tok >= NTOK) return;
    const float* xr = x + (size_t)tok * Dc;
    float acc[Ec];
#pragma unroll
    for (int e = 0; e < Ec; e++) acc[e] = 0.0f;
    for (int d = lane; d < Dc; d += 32) {
        float xv = xr[d];
        const float4* wr = (const float4*)(Wg + (size_t)d * Ec);
        float4 w0 = wr[0], w1 = wr[1];
        acc[0] += xv * w0.x; acc[1] += xv * w0.y; acc[2] += xv * w0.z; acc[3] += xv * w0.w;
        acc[4] += xv * w1.x; acc[5] += xv * w1.y; acc[6] += xv * w1.z; acc[7] += xv * w1.w;
    }
#pragma unroll
    for (int e = 0; e < Ec; e++)
#pragma unroll
        for (int off = 16; off > 0; off >>= 1)
            acc[e] += __shfl_down_sync(0xFFFFFFFFu, acc[e], off);
    if (lane == 0) {
        float v[Ec];
#pragma unroll
        for (int e = 0; e < Ec; e++) v[e] = acc[e] + bg[e];
        int b0 = 0;
#pragma unroll
        for (int e = 1; e < Ec; e++) if (v[e] > v[b0]) b0 = e;
        int b1 = -1; float s = -1e30f;
#pragma unroll
        for (int e = 0; e < Ec; e++) { if (e == b0) continue; if (v[e] > s) { s = v[e]; b1 = e; } }
        float ed = expf(s - v[b0]);
        float p0 = 1.0f / (1.0f + ed);
        float p1 = ed * p0;
        g_tok_e[tok * 2 + 0] = b0; g_tok_e[tok * 2 + 1] = b1;
        g_tok_w[tok * 2 + 0] = p0; g_tok_w[tok * 2 + 1] = p1;
    }
}

// ---------------- scatter: single block builds counts, tiles, perm -----------
__global__ void k_scatter() {
    __shared__ int cnt[Ec], cur[Ec];
    int tid = threadIdx.x;
    if (tid < Ec) cnt[tid] = 0;
    __syncthreads();
    for (int t = tid; t < NTOK; t += 1024) {
        atomicAdd(&cnt[g_tok_e[2 * t]], 1);
        atomicAdd(&cnt[g_tok_e[2 * t + 1]], 1);
    }
    __syncthreads();
    if (tid == 0) {
        int o = 0, nt = 0;
        for (int e = 0; e < Ec; e++) {
            int c = cnt[e];
            cur[e] = o;
            for (int s = 0; s < c; s += BM) {
                g_tile_base[nt] = o + s; g_tile_expert[nt] = e;
                g_tile_rows[nt] = min(BM, c - s); nt++;
            }
            o += c;
        }
        g_ntiles = nt;
    }
    __syncthreads();
    for (int t = tid; t < NTOK; t += 1024) {
#pragma unroll
        for (int k = 0; k < 2; k++) {
            int e = g_tok_e[2 * t + k];
            int pos = atomicAdd(&cur[e], 1);
            g_perm[pos] = t;
            g_tok_slot[2 * t + k] = pos;
        }
    }
}

// ---------------- gather x rows -> slot-order fp16 (float4 loads) ------------
__global__ void k_gather(const float* __restrict__ x) {
    int s = blockIdx.x;
    int tid = threadIdx.x;
    if (s < NSLOT) {
        const float4* src = (const float4*)(x + (size_t)g_perm[s] * Dc);
        float4 v = __ldg(&src[tid]);
        uint32_t lo = pack2(__float2half_rn(v.x), __float2half_rn(v.y));
        uint32_t hi = pack2(__float2half_rn(v.z), __float2half_rn(v.w));
        uint2 o; o.x = lo; o.y = hi;
        *(uint2*)(g_xg + (size_t)s * Dc + tid * 4) = o;
    } else {
        uint2 z; z.x = 0u; z.y = 0u;
        *(uint2*)(g_xg + (size_t)s * Dc + tid * 4) = z;
    }
}

// ---------------- weight transpose: in [e][R][C] fp32 -> out [e][C][R] fp16 --
__global__ void k_tsplit(const float* __restrict__ in, int which, int R, int C) {
    fp16* o = which ? g_W2t : g_W1t;
    __shared__ float t[32][33];
    int e = blockIdx.z;
    int r0 = blockIdx.y * 32, c0 = blockIdx.x * 32;
    int tx = threadIdx.x, ty = threadIdx.y;
    const float* base = in + (size_t)e * R * C;
#pragma unroll
    for (int i = 0; i < 4; i++)
        t[ty + 8 * i][tx] = base[(size_t)(r0 + ty + 8 * i) * C + c0 + tx];
    __syncthreads();
    size_t ob = (size_t)e * C * R;
#pragma unroll
    for (int i = 0; i < 4; i++) {
        float v = t[tx][ty + 8 * i];
        o[ob + (size_t)(c0 + ty + 8 * i) * R + r0 + tx] = __float2half_rn(v);
    }
}

// ---------------- GEMM core (R7 arithmetic; 5-stage pipeline) -----------------
// CTA 128x128x32, 8 warps in 4(M) x 2(N) grid, warp tile 32x64. 2 CTAs/SM.
__device__ __forceinline__ void load_stage(uint32_t sb,
        const fp16* __restrict__ A, const fp16* __restrict__ B,
        int ldk, int k0, int tid) {
#pragma unroll
    for (int i = 0; i < 2; i++) {
        int idx = tid * 2 + i;
        int row = idx >> 2, cpos = idx & 3;
        uint32_t so = (uint32_t)row * ROWB + cpos * 16;
        size_t go = (size_t)row * ldk + k0 + cpos * 8;
        cp16(sb + ST_A + so, A + go);
        cp16(sb + ST_B + so, B + go);
    }
}

__device__ __forceinline__ void gemm_core(uint32_t sm0,
        const fp16* __restrict__ A, const fp16* __restrict__ B,
        int ldk, int NC, int tid, float (&acc)[2][8][4]) {
    const int lane = tid & 31, wid = tid >> 5;
    const int wm = (wid & 3) * 32, wn = (wid >> 2) * 64;

    const uint32_t a_off = (uint32_t)(wm + (lane & 15)) * ROWB + ((lane & 16) ? 16u : 0u);
    const uint32_t b_off = (uint32_t)(wn + (lane & 7) + ((lane & 16) >> 1)) * ROWB
                           + ((lane & 8) ? 16u : 0u);

#pragma unroll
    for (int mt = 0; mt < 2; mt++)
#pragma unroll
        for (int nt = 0; nt < 8; nt++)
#pragma unroll
            for (int q = 0; q < 4; q++) acc[mt][nt][q] = 0.0f;

    // prologue: 4 stages in flight
#pragma unroll
    for (int s = 0; s < 4; s++) {
        load_stage(sm0 + (uint32_t)s * STAGE, A, B, ldk, s * BK, tid);
        cp_commit();
    }

    int stg = 0, pre = 4;
    for (int k = 0; k < NC; k++) {
        int rem = NC - 1 - k;
        if (rem >= 3)      { CP_WAIT(3); }
        else if (rem == 2) { CP_WAIT(2); }
        else if (rem == 1) { CP_WAIT(1); }
        else               { CP_WAIT(0); }
        __syncthreads();
        if (k + 4 < NC) {
            load_stage(sm0 + (uint32_t)pre * STAGE, A, B, ldk, (k + 4) * BK, tid);
            cp_commit();
            if (++pre == NSTG) pre = 0;
        }
        uint32_t sb = sm0 + (uint32_t)stg * STAGE;
#pragma unroll
        for (int kk = 0; kk < 2; kk++) {
            const uint32_t kb = kk * 32;
            uint32_t ah[2][4], bh[4][4];
#pragma unroll
            for (int mt = 0; mt < 2; mt++)
                ldmx4(sb + ST_A + a_off + mt * 16 * ROWB + kb, ah[mt]);
#pragma unroll
            for (int p = 0; p < 4; p++)
                ldmx4(sb + ST_B + b_off + p * 16 * ROWB + kb, bh[p]);
#pragma unroll
            for (int p = 0; p < 4; p++)
#pragma unroll
                for (int q = 0; q < 2; q++)
#pragma unroll
                    for (int mt = 0; mt < 2; mt++)
                        mma16816(acc[mt][p * 2 + q], ah[mt], &bh[p][q * 2]);
        }
        __syncthreads();
        if (++stg == NSTG) stg = 0;
    }
}

// ---------------- GEMM1: h = fp16(gelu(xg @ W1t^T + b1)) ----------------------
__global__ void __launch_bounds__(256, 2)
k_mma1(const float* __restrict__ b1) {
    int t = blockIdx.y;
    if (t >= g_ntiles) return;
    const int n0 = blockIdx.x * BN;
    const int base = g_tile_base[t], e = g_tile_expert[t], rows = g_tile_rows[t];

    extern __shared__ char dsm[];
    uint32_t sm0 = smem_u32(dsm);
    int tid = threadIdx.x;

    float acc[2][8][4];
    gemm_core(sm0, g_xg + (size_t)base * Dc,
              g_W1t + ((size_t)e * Fc + n0) * Dc, Dc, Dc / BK, tid, acc);

    const int lane = tid & 31, wid = tid >> 5;
    const int wm = (wid & 3) * 32, wn = (wid >> 2) * 64;
    const int rb = wm + (lane >> 2);
    const int cb = wn + (lane & 3) * 2;
    const float* b1e = b1 + (size_t)e * Fc + n0;
    float bv[8][2];
#pragma unroll
    for (int nt = 0; nt < 8; nt++) {
        bv[nt][0] = b1e[cb + nt * 8];
        bv[nt][1] = b1e[cb + nt * 8 + 1];
    }
#pragma unroll
    for (int mt = 0; mt < 2; mt++)
#pragma unroll
        for (int half = 0; half < 2; half++) {
            int r = rb + mt * 16 + half * 8;
            if (r >= rows) continue;
            size_t ro = (size_t)(base + r) * Fc + n0;
#pragma unroll
            for (int nt = 0; nt < 8; nt++) {
                float v0 = gelu_exact(acc[mt][nt][half * 2 + 0] + bv[nt][0]);
                float v1 = gelu_exact(acc[mt][nt][half * 2 + 1] + bv[nt][1]);
                *(uint32_t*)(g_h + ro + cb + nt * 8) =
                    pack2(__float2half_rn(v0), __float2half_rn(v1));
            }
        }
}

// ---------------- GEMM2: y[slot] = fp16(h @ W2t^T + b2) -----------------------
__global__ void __launch_bounds__(256, 2)
k_mma2(const float* __restrict__ b2) {
    int t = blockIdx.y;
    if (t >= g_ntiles) return;
    const int n0 = blockIdx.x * BN;
    const int base = g_tile_base[t], e = g_tile_expert[t], rows = g_tile_rows[t];

    extern __shared__ char dsm[];
    uint32_t sm0 = smem_u32(dsm);
    int tid = threadIdx.x;

    float acc[2][8][4];
    gemm_core(sm0, g_h + (size_t)base * Fc,
              g_W2t + ((size_t)e * Dc + n0) * Fc, Fc, Fc / BK, tid, acc);

    const int lane = tid & 31, wid = tid >> 5;
    const int wm = (wid & 3) * 32, wn = (wid >> 2) * 64;
    const int rb = wm + (lane >> 2);
    const int cb = wn + (lane & 3) * 2;
    const float* b2e = b2 + (size_t)e * Dc + n0;
    float bv[8][2];
#pragma unroll
    for (int nt = 0; nt < 8; nt++) {
        bv[nt][0] = b2e[cb + nt * 8];
        bv[nt][1] = b2e[cb + nt * 8 + 1];
    }
#pragma unroll
    for (int mt = 0; mt < 2; mt++)
#pragma unroll
        for (int half = 0; half < 2; half++) {
            int r = rb + mt * 16 + half * 8;
            if (r >= rows) continue;
            fp16* yrow = g_y + (size_t)(base + r) * Dc + n0;
#pragma unroll
            for (int nt = 0; nt < 8; nt++) {
                int c = cb + nt * 8;
                float v0 = acc[mt][nt][half * 2 + 0] + bv[nt][0];
                float v1 = acc[mt][nt][half * 2 + 1] + bv[nt][1];
                *(uint32_t*)(yrow + c) =
                    pack2(__float2half_rn(v0), __float2half_rn(v1));
            }
        }
}

// ---------------- combine: out[t] = w0*y[s0] + w1*y[s1] -----------------------
__global__ void k_combine(float* __restrict__ out) {
    int t = blockIdx.x;
    int tid = threadIdx.x;
    int s0 = g_tok_slot[t * 2 + 0], s1 = g_tok_slot[t * 2 + 1];
    float w0 = g_tok_w[t * 2 + 0],  w1 = g_tok_w[t * 2 + 1];
    // 4 fp16 per thread from each slot row (Dc/4 = 256 groups, 256 threads)
    const uint2* y0 = (const uint2*)(g_y + (size_t)s0 * Dc);
    const uint2* y1 = (const uint2*)(g_y + (size_t)s1 * Dc);
    uint2 a = __ldg(&y0[tid]);
    uint2 b = __ldg(&y1[tid]);
    __half2 a0 = *(__half2*)&a.x, a1 = *(__half2*)&a.y;
    __half2 b0 = *(__half2*)&b.x, b1 = *(__half2*)&b.y;
    float2 fa0 = __half22float2(a0), fa1 = __half22float2(a1);
    float2 fb0 = __half22float2(b0), fb1 = __half22float2(b1);
    float4 r;
    r.x = w0 * fa0.x + w1 * fb0.x;
    r.y = w0 * fa0.y + w1 * fb0.y;
    r.z = w0 * fa1.x + w1 * fb1.x;
    r.w = w0 * fa1.y + w1 * fb1.y;
    ((float4*)(out + (size_t)t * Dc))[tid] = r;
}

// ---------------- launch (R13 stream fork-join) --------------------------------
extern "C" void kernel_launch(void* const* d_in, const int* in_sizes, int n_in,
                              void* d_out, int out_size) {
    const float* x  = (const float*)d_in[0];
    const float* Wg = (const float*)d_in[1];
    const float* bg = (const float*)d_in[2];
    const float* W1 = (const float*)d_in[3];
    const float* b1 = (const float*)d_in[4];
    const float* W2 = (const float*)d_in[5];
    const float* b2 = (const float*)d_in[6];
    float* out = (float*)d_out;

    static cudaStream_t s1 = nullptr, s2 = nullptr;
    static cudaEvent_t e_root = nullptr, e_w1 = nullptr, e_w2 = nullptr;
    static int configured = 0;
    if (!configured) {
        cudaFuncSetAttribute(k_mma1, cudaFuncAttributeMaxDynamicSharedMemorySize, SMEM_DYN);
        cudaFuncSetAttribute(k_mma2, cudaFuncAttributeMaxDynamicSharedMemorySize, SMEM_DYN);
        cudaStreamCreateWithFlags(&s1, cudaStreamNonBlocking);
        cudaStreamCreateWithFlags(&s2, cudaStreamNonBlocking);
        cudaEventCreateWithFlags(&e_root, cudaEventDisableTiming);
        cudaEventCreateWithFlags(&e_w1, cudaEventDisableTiming);
        cudaEventCreateWithFlags(&e_w2, cudaEventDisableTiming);
        configured = 1;
    }

    // fork: weight conversions on side streams (start at t=0)
    cudaEventRecord(e_root, 0);
    cudaStreamWaitEvent(s1, e_root, 0);
    cudaStreamWaitEvent(s2, e_root, 0);
    k_tsplit<<<dim3(Fc / 32, Dc / 32, Ec), dim3(32, 8), 0, s1>>>(W1, 0, Dc, Fc);
    cudaEventRecord(e_w1, s1);
    k_tsplit<<<dim3(Dc / 32, Fc / 32, Ec), dim3(32, 8), 0, s2>>>(W2, 1, Fc, Dc);
    cudaEventRecord(e_w2, s2);

    // main stream: routing chain (overlaps W1/W2 conversion)
    k_gate<<<NTOK / 8, 256>>>(x, Wg, bg);
    k_scatter<<<1, 1024>>>();
    k_gather<<<NSLOT + PADR, 256>>>(x);

    // join W1 before GEMM1; W2 conversion keeps running under GEMM1
    cudaStreamWaitEvent(0, e_w1, 0);
    k_mma1<<<dim3(Fc / BN, MAX_TILES), 256, SMEM_DYN>>>(b1);

    // join W2 before GEMM2
    cudaStreamWaitEvent(0, e_w2, 0);
    k_mma2<<<dim3(Dc / BN, MAX_TILES), 256, SMEM_DYN>>>(b2);
    k_combine<<<NTOK, 256>>>(out);
}

// round 15
// speedup vs baseline: 1.5319x; 1.4504x over previous
#include <cuda_runtime.h>
#include <cuda_fp16.h>
#include <math.h>
#include <stdint.h>

typedef __half fp16;

#define Dc   1024
#define Ec   8
#define Fc   4096
#define NTOK 8192
#define NSLOT (NTOK * 2)
#define MAX_TILES 136
#define NSLOT_PAD (MAX_TILES * 128)   // 17408 padded slots
#define BM 128
#define BN 128
#define BK 32

// blocked operand storage: 8KB block = 128 rows x 32 cols fp16, swizzled
#define BLKB 8192
#define STAGE (2 * BLKB)            // A block + B block = 16384 B
#define NSTG 5
#define SMEM_DYN (NSTG * STAGE + 256)  // stages + mbarriers + align slack

// ---------------- scratch (device globals) ---------------------------------
__device__ __align__(1024) fp16  g_xg [(size_t)NSLOT_PAD * Dc];   // blocked
__device__ __align__(1024) fp16  g_h  [(size_t)NSLOT_PAD * Fc];   // blocked
__device__ __align__(1024) fp16  g_y  [(size_t)NSLOT_PAD * Dc];   // linear, fp16
__device__ __align__(1024) fp16  g_W1t[(size_t)Ec * Fc * Dc];     // blocked per expert
__device__ __align__(1024) fp16  g_W2t[(size_t)Ec * Dc * Fc];     // blocked per expert
__device__ int   g_perm[NSLOT_PAD];
__device__ int   g_tok_slot[NTOK * 2];
__device__ int   g_tok_e[NTOK * 2];
__device__ float g_tok_w[NTOK * 2];
__device__ int   g_tile_expert[MAX_TILES];
__device__ int   g_ntiles;

// ---------------- helpers ----------------------------------------------------
__device__ __forceinline__ uint32_t smem_u32(const void* p) {
    uint32_t a;
    asm("{ .reg .u64 t; cvta.to.shared.u64 t, %1; cvt.u32.u64 %0, t; }" : "=r"(a) : "l"(p));
    return a;
}
__device__ __forceinline__ uint32_t swz64(uint32_t o) { return o ^ ((o >> 3) & 0x30); }

// blocked byte offset within a matrix of nblkcols K-chunks per 128-row band
__device__ __forceinline__ size_t blk_off(int nblkcols, int row, int col) {
    return ((size_t)(row >> 7) * nblkcols + (col >> 5)) * BLKB
         + swz64((uint32_t)((row & 127) << 6) + (uint32_t)((col & 31) << 1));
}

#define MBARRIER_INIT(mb, cnt) asm volatile("mbarrier.init.shared.b64 [%0], %1;" :: "r"(mb), "r"(cnt) : "memory")
#define MBARRIER_EXPECT_TX(mb, tx) asm volatile("mbarrier.arrive.expect_tx.shared.b64 _, [%0], %1;" :: "r"(mb), "r"(tx) : "memory")
#define MBARRIER_WAIT_PARITY(mb, ph) do {                                                   \
    uint32_t _m = (mb), _p = (ph), _d;                                                      \
    asm volatile("{\n\t.reg .pred p;\n\t"                                                   \
        "mbarrier.try_wait.parity.acquire.cta.shared::cta.b64 p, [%1], %2;\n\t"             \
        "selp.b32 %0, 1, 0, p;\n\t}" : "=r"(_d) : "r"(_m), "r"(_p) : "memory");             \
    if (!_d) {                                                                              \
        asm volatile("{\n\t.reg .pred P1;\n\tWL_%=:\n\t"                                    \
            "mbarrier.try_wait.parity.acquire.cta.shared::cta.b64 P1, [%0], %1, 0x989680;\n\t" \
            "@P1 bra.uni WD_%=;\n\tbra.uni WL_%=;\n\tWD_%=:\n\t}"                           \
            :: "r"(_m), "r"(_p) : "memory");                                                \
    }                                                                                       \
} while (0)

__device__ __forceinline__ void bulk_cp(uint32_t sdst, const void* gsrc, uint32_t bytes,
                                        uint32_t mbar) {
    asm volatile(
        "cp.async.bulk.shared::cta.global.mbarrier::complete_tx::bytes [%0], [%1], %2, [%3];"
        :: "r"(sdst), "l"(gsrc), "r"(bytes), "r"(mbar) : "memory");
}

__device__ __forceinline__ void ldmx4(uint32_t addr, uint32_t r[4]) {
    asm volatile("ldmatrix.sync.aligned.m8n8.x4.shared.b16 {%0,%1,%2,%3}, [%4];"
        : "=r"(r[0]), "=r"(r[1]), "=r"(r[2]), "=r"(r[3]) : "r"(addr));
}
__device__ __forceinline__ void mma16816(float c[4], const uint32_t a[4], const uint32_t* b) {
    asm volatile("mma.sync.aligned.m16n8k16.row.col.f32.f16.f16.f32 "
        "{%0,%1,%2,%3}, {%4,%5,%6,%7}, {%8,%9}, {%0,%1,%2,%3};"
        : "+f"(c[0]), "+f"(c[1]), "+f"(c[2]), "+f"(c[3])
        : "r"(a[0]), "r"(a[1]), "r"(a[2]), "r"(a[3]), "r"(b[0]), "r"(b[1]));
}
__device__ __forceinline__ float gelu_exact(float v) {
    return 0.5f * v * (1.0f + erff(v * 0.70710678118654752f));
}
__device__ __forceinline__ uint32_t pack2(fp16 a, fp16 b) {
    return (uint32_t)__half_as_ushort(a) | ((uint32_t)__half_as_ushort(b) << 16);
}

// ---------------- gate (fp32, exact routing) ---------------------------------
__global__ void k_gate(const float* __restrict__ x, const float* __restrict__ Wg,
                       const float* __restrict__ bg) {
    int gtid = blockIdx.x * blockDim.x + threadIdx.x;
    int tok = gtid >> 5, lane = gtid & 31;
    if (tok >= NTOK) return;
    const float* xr = x + (size_t)tok * Dc;
    float acc[Ec];
#pragma unroll
    for (int e = 0; e < Ec; e++) acc[e] = 0.0f;
    for (int d = lane; d < Dc; d += 32) {
        float xv = xr[d];
        const float4* wr = (const float4*)(Wg + (size_t)d * Ec);
        float4 w0 = wr[0], w1 = wr[1];
        acc[0] += xv * w0.x; acc[1] += xv * w0.y; acc[2] += xv * w0.z; acc[3] += xv * w0.w;
        acc[4] += xv * w1.x; acc[5] += xv * w1.y; acc[6] += xv * w1.z; acc[7] += xv * w1.w;
    }
#pragma unroll
    for (int e = 0; e < Ec; e++)
#pragma unroll
        for (int off = 16; off > 0; off >>= 1)
            acc[e] += __shfl_down_sync(0xFFFFFFFFu, acc[e], off);
    if (lane == 0) {
        float v[Ec];
#pragma unroll
        for (int e = 0; e < Ec; e++) v[e] = acc[e] + bg[e];
        int b0 = 0;
#pragma unroll
        for (int e = 1; e < Ec; e++) if (v[e] > v[b0]) b0 = e;
        int b1 = -1; float s = -1e30f;
#pragma unroll
        for (int e = 0; e < Ec; e++) { if (e == b0) continue; if (v[e] > s) { s = v[e]; b1 = e; } }
        float ed = expf(s - v[b0]);
        float p0 = 1.0f / (1.0f + ed);
        float p1 = ed * p0;
        g_tok_e[tok * 2 + 0] = b0; g_tok_e[tok * 2 + 1] = b1;
        g_tok_w[tok * 2 + 0] = p0; g_tok_w[tok * 2 + 1] = p1;
    }
}

// ---------------- scatter: counts, padded prefix, tiles, perm ----------------
__global__ void k_scatter() {
    __shared__ int cnt[Ec], cur[Ec];
    int tid = threadIdx.x;
    for (int s = tid; s < NSLOT_PAD; s += 1024) g_perm[s] = -1;
    if (tid < Ec) cnt[tid] = 0;
    __syncthreads();
    for (int t = tid; t < NTOK; t += 1024) {
        atomicAdd(&cnt[g_tok_e[2 * t]], 1);
        atomicAdd(&cnt[g_tok_e[2 * t + 1]], 1);
    }
    __syncthreads();
    if (tid == 0) {
        int o = 0, nt = 0;
        for (int e = 0; e < Ec; e++) {
            int c = cnt[e];
            cur[e] = o;
            int ntl = (c + 127) >> 7;
            for (int i = 0; i < ntl; i++) g_tile_expert[nt++] = e;
            o += ntl << 7;                  // pad each expert segment to 128
        }
        g_ntiles = nt;
    }
    __syncthreads();
    for (int t = tid; t < NTOK; t += 1024) {
#pragma unroll
        for (int k = 0; k < 2; k++) {
            int e = g_tok_e[2 * t + k];
            int pos = atomicAdd(&cur[e], 1);
            g_perm[pos] = t;
            g_tok_slot[2 * t + k] = pos;
        }
    }
}

// ---------------- gather x rows -> blocked swizzled fp16 ----------------------
__global__ void k_gather(const float* __restrict__ x) {
    int s = blockIdx.x;                 // padded slot
    int tid = threadIdx.x;
    int d = tid * 4;                    // 4 fp16 per thread
    int p = g_perm[s];
    uint2 o2;
    if (p >= 0) {
        float4 v = __ldg((const float4*)(x + (size_t)p * Dc + d));
        o2.x = pack2(__float2half_rn(v.x), __float2half_rn(v.y));
        o2.y = pack2(__float2half_rn(v.z), __float2half_rn(v.w));
    } else {
        o2.x = 0u; o2.y = 0u;
    }
    char* dst = (char*)g_xg + ((size_t)(s >> 7) * (Dc / 32) + (d >> 5)) * BLKB
              + swz64((uint32_t)((s & 127) << 6) + (uint32_t)((d & 31) << 1));
    *(uint2*)dst = o2;
}

// ---------------- weight transpose -> blocked swizzled fp16 -------------------
// in [e][R][C] fp32; operand rows = C-index, cols(K) = R-index
__global__ void k_tsplit(const float* __restrict__ in, int which, int R, int C) {
    fp16* o = which ? g_W2t : g_W1t;
    __shared__ float t[32][33];
    int e = blockIdx.z;
    int r0 = blockIdx.y * 32, c0 = blockIdx.x * 32;
    int tx = threadIdx.x, ty = threadIdx.y;
    const float* base = in + (size_t)e * R * C;
#pragma unroll
    for (int i = 0; i < 4; i++)
        t[ty + 8 * i][tx] = base[(size_t)(r0 + ty + 8 * i) * C + c0 + tx];
    __syncthreads();
    char* ob = (char*)o + (size_t)e * R * C * 2;
#pragma unroll
    for (int i = 0; i < 4; i++) {
        float v = t[tx][ty + 8 * i];
        int row = c0 + ty + 8 * i;      // C index (operand row)
        int col = r0 + tx;              // R index (K)
        *(fp16*)(ob + blk_off(R / 32, row, col)) = __float2half_rn(v);
    }
}

// ---------------- GEMM core: bulk-DMA pipeline --------------------------------
// CTA 128x128x32, 8 warps 4(M) x 2(N), warp tile 32x64. 2 CTAs/SM.
// Per stage: 2 x cp.async.bulk (8KB A blk + 8KB B blk) issued by thread 0.
__device__ __forceinline__ void gemm_core(uint32_t sm0,
        const char* __restrict__ Ab, const char* __restrict__ Bb,
        int NC, int tid, float (&acc)[2][8][4]) {
    const int lane = tid & 31, wid = tid >> 5;
    const int wm = (wid & 3) * 32, wn = (wid >> 2) * 64;
    const uint32_t mb0 = sm0 + NSTG * STAGE;

    const uint32_t aBase = (uint32_t)(wm + (lane & 15)) * 64 + ((lane & 16) ? 16u : 0u);
    const uint32_t bBase = (uint32_t)(wn + (lane & 7) + ((lane & 16) >> 1)) * 64
                           + ((lane & 8) ? 16u : 0u);
    const uint32_t aMask = (aBase >> 3) & 0x30;
    const uint32_t bMask = (bBase >> 3) & 0x30;

#pragma unroll
    for (int mt = 0; mt < 2; mt++)
#pragma unroll
        for (int nt = 0; nt < 8; nt++)
#pragma unroll
            for (int q = 0; q < 4; q++) acc[mt][nt][q] = 0.0f;

    if (tid == 0) {
#pragma unroll
        for (int s = 0; s < NSTG; s++) MBARRIER_INIT(mb0 + 8 * s, 1);
    }
    __syncthreads();

    if (tid == 0) {
#pragma unroll
        for (int s = 0; s < 4; s++) {
            uint32_t mb = mb0 + 8 * s;
            MBARRIER_EXPECT_TX(mb, STAGE);
            bulk_cp(sm0 + s * STAGE,        Ab + (size_t)s * BLKB, BLKB, mb);
            bulk_cp(sm0 + s * STAGE + BLKB, Bb + (size_t)s * BLKB, BLKB, mb);
        }
    }

    for (int k = 0; k < NC; k++) {
        int slot = k % NSTG;
        MBARRIER_WAIT_PARITY(mb0 + 8 * slot, (k / NSTG) & 1);
        if (tid == 0 && k + 4 < NC) {
            int s2 = (k + 4) % NSTG;
            uint32_t mb = mb0 + 8 * s2;
            MBARRIER_EXPECT_TX(mb, STAGE);
            bulk_cp(sm0 + s2 * STAGE,        Ab + (size_t)(k + 4) * BLKB, BLKB, mb);
            bulk_cp(sm0 + s2 * STAGE + BLKB, Bb + (size_t)(k + 4) * BLKB, BLKB, mb);
        }
        uint32_t sa = sm0 + slot * STAGE;
        uint32_t sb = sa + BLKB;
#pragma unroll
        for (int kk = 0; kk < 2; kk++) {
            const uint32_t kb = kk * 32;
            uint32_t ah[2][4], bh[4][4];
#pragma unroll
            for (int mt = 0; mt < 2; mt++)
                ldmx4(sa + ((aBase + mt * 1024 + kb) ^ aMask), ah[mt]);
#pragma unroll
            for (int p = 0; p < 4; p++)
                ldmx4(sb + ((bBase + p * 1024 + kb) ^ bMask), bh[p]);
#pragma unroll
            for (int p = 0; p < 4; p++)
#pragma unroll
                for (int q = 0; q < 2; q++)
#pragma unroll
                    for (int mt = 0; mt < 2; mt++)
                        mma16816(acc[mt][p * 2 + q], ah[mt], &bh[p][q * 2]);
        }
        __syncthreads();
    }
}

// ---------------- GEMM1: h_blk = fp16(gelu(xg_blk @ W1^T + b1)) ---------------
__global__ void __launch_bounds__(256, 2)
k_mma1(const float* __restrict__ b1) {
    int t = blockIdx.y;
    if (t >= g_ntiles) return;
    const int n0 = blockIdx.x * BN;
    const int e = g_tile_expert[t];

    extern __shared__ char dsm[];
    uint32_t sm0 = (smem_u32(dsm) + 127u) & ~127u;
    int tid = threadIdx.x;

    const char* Ab = (const char*)g_xg + (size_t)t * (Dc / 32) * BLKB;
    const char* Bb = (const char*)g_W1t + (size_t)e * Fc * Dc * 2
                   + (size_t)blockIdx.x * (Dc / 32) * BLKB;

    float acc[2][8][4];
    gemm_core(sm0, Ab, Bb, Dc / BK, tid, acc);

    const int lane = tid & 31, wid = tid >> 5;
    const int wm = (wid & 3) * 32, wn = (wid >> 2) * 64;
    const int rb = wm + (lane >> 2);
    const int cb = wn + (lane & 3) * 2;
    const float* b1e = b1 + (size_t)e * Fc + n0;
    float bv[8][2];
#pragma unroll
    for (int nt = 0; nt < 8; nt++) {
        bv[nt][0] = b1e[cb + nt * 8];
        bv[nt][1] = b1e[cb + nt * 8 + 1];
    }
    char* hb = (char*)g_h + (size_t)t * (Fc / 32) * BLKB;
#pragma unroll
    for (int mt = 0; mt < 2; mt++)
#pragma unroll
        for (int half = 0; half < 2; half++) {
            int r = rb + mt * 16 + half * 8;
#pragma unroll
            for (int nt = 0; nt < 8; nt++) {
                int gc = n0 + cb + nt * 8;
                float v0 = gelu_exact(acc[mt][nt][half * 2 + 0] + bv[nt][0]);
                float v1 = gelu_exact(acc[mt][nt][half * 2 + 1] + bv[nt][1]);
                char* dst = hb + (size_t)(gc >> 5) * BLKB
                          + swz64((uint32_t)(r << 6) + (uint32_t)((gc & 31) << 1));
                *(uint32_t*)dst = pack2(__float2half_rn(v0), __float2half_rn(v1));
            }
        }
}

// ---------------- GEMM2: y[slot] = fp16(h_blk @ W2^T + b2) --------------------
__global__ void __launch_bounds__(256, 2)
k_mma2(const float* __restrict__ b2) {
    int t = blockIdx.y;
    if (t >= g_ntiles) return;
    const int n0 = blockIdx.x * BN;
    const int e = g_tile_expert[t];

    extern __shared__ char dsm[];
    uint32_t sm0 = (smem_u32(dsm) + 127u) & ~127u;
    int tid = threadIdx.x;

    const char* Ab = (const char*)g_h + (size_t)t * (Fc / 32) * BLKB;
    const char* Bb = (const char*)g_W2t + (size_t)e * Dc * Fc * 2
                   + (size_t)blockIdx.x * (Fc / 32) * BLKB;

    float acc[2][8][4];
    gemm_core(sm0, Ab, Bb, Fc / BK, tid, acc);

    const int lane = tid & 31, wid = tid >> 5;
    const int wm = (wid & 3) * 32, wn = (wid >> 2) * 64;
    const int rb = wm + (lane >> 2);
    const int cb = wn + (lane & 3) * 2;
    const float* b2e = b2 + (size_t)e * Dc + n0;
    float bv[8][2];
#pragma unroll
    for (int nt = 0; nt < 8; nt++) {
        bv[nt][0] = b2e[cb + nt * 8];
        bv[nt][1] = b2e[cb + nt * 8 + 1];
    }
#pragma unroll
    for (int mt = 0; mt < 2; mt++)
#pragma unroll
        for (int half = 0; half < 2; half++) {
            int r = rb + mt * 16 + half * 8;
            fp16* yrow = g_y + (size_t)(t * 128 + r) * Dc + n0;
#pragma unroll
            for (int nt = 0; nt < 8; nt++) {
                int c = cb + nt * 8;
                float v0 = acc[mt][nt][half * 2 + 0] + bv[nt][0];
                float v1 = acc[mt][nt][half * 2 + 1] + bv[nt][1];
                *(uint32_t*)(yrow + c) = pack2(__float2half_rn(v0), __float2half_rn(v1));
            }
        }
}

// ---------------- combine: out[t] = w0*y[s0] + w1*y[s1] -----------------------
__global__ void k_combine(float* __restrict__ out) {
    int t = blockIdx.x;
    int tid = threadIdx.x;
    int s0 = g_tok_slot[t * 2 + 0], s1 = g_tok_slot[t * 2 + 1];
    float w0 = g_tok_w[t * 2 + 0],  w1 = g_tok_w[t * 2 + 1];
    const uint2* y0 = (const uint2*)(g_y + (size_t)s0 * Dc);
    const uint2* y1 = (const uint2*)(g_y + (size_t)s1 * Dc);
    uint2 a = __ldg(&y0[tid]);
    uint2 b = __ldg(&y1[tid]);
    __half2 a0 = *(__half2*)&a.x, a1 = *(__half2*)&a.y;
    __half2 b0 = *(__half2*)&b.x, b1 = *(__half2*)&b.y;
    float2 fa0 = __half22float2(a0), fa1 = __half22float2(a1);
    float2 fb0 = __half22float2(b0), fb1 = __half22float2(b1);
    float4 r;
    r.x = w0 * fa0.x + w1 * fb0.x;
    r.y = w0 * fa0.y + w1 * fb0.y;
    r.z = w0 * fa1.x + w1 * fb1.x;
    r.w = w0 * fa1.y + w1 * fb1.y;
    ((float4*)(out + (size_t)t * Dc))[tid] = r;
}

// ---------------- launch (stream fork-join as champion) -----------------------
extern "C" void kernel_launch(void* const* d_in, const int* in_sizes, int n_in,
                              void* d_out, int out_size) {
    const float* x  = (const float*)d_in[0];
    const float* Wg = (const float*)d_in[1];
    const float* bg = (const float*)d_in[2];
    const float* W1 = (const float*)d_in[3];
    const float* b1 = (const float*)d_in[4];
    const float* W2 = (const float*)d_in[5];
    const float* b2 = (const float*)d_in[6];
    float* out = (float*)d_out;

    static cudaStream_t s1 = nullptr, s2 = nullptr;
    static cudaEvent_t e_root = nullptr, e_w1 = nullptr, e_w2 = nullptr;
    static int configured = 0;
    if (!configured) {
        cudaFuncSetAttribute(k_mma1, cudaFuncAttributeMaxDynamicSharedMemorySize, SMEM_DYN);
        cudaFuncSetAttribute(k_mma2, cudaFuncAttributeMaxDynamicSharedMemorySize, SMEM_DYN);
        cudaStreamCreateWithFlags(&s1, cudaStreamNonBlocking);
        cudaStreamCreateWithFlags(&s2, cudaStreamNonBlocking);
        cudaEventCreateWithFlags(&e_root, cudaEventDisableTiming);
        cudaEventCreateWithFlags(&e_w1, cudaEventDisableTiming);
        cudaEventCreateWithFlags(&e_w2, cudaEventDisableTiming);
        configured = 1;
    }

    cudaEventRecord(e_root, 0);
    cudaStreamWaitEvent(s1, e_root, 0);
    cudaStreamWaitEvent(s2, e_root, 0);
    k_tsplit<<<dim3(Fc / 32, Dc / 32, Ec), dim3(32, 8), 0, s1>>>(W1, 0, Dc, Fc);
    cudaEventRecord(e_w1, s1);
    k_tsplit<<<dim3(Dc / 32, Fc / 32, Ec), dim3(32, 8), 0, s2>>>(W2, 1, Fc, Dc);
    cudaEventRecord(e_w2, s2);

    k_gate<<<NTOK / 8, 256>>>(x, Wg, bg);
    k_scatter<<<1, 1024>>>();
    k_gather<<<NSLOT_PAD, 256>>>(x);

    cudaStreamWaitEvent(0, e_w1, 0);
    k_mma1<<<dim3(Fc / BN, MAX_TILES), 256, SMEM_DYN>>>(b1);

    cudaStreamWaitEvent(0, e_w2, 0);
    k_mma2<<<dim3(Dc / BN, MAX_TILES), 256, SMEM_DYN>>>(b2);
    k_combine<<<NTOK, 256>>>(out);
}

// round 16
// speedup vs baseline: 1.6224x; 1.0591x over previous
#include <cuda_runtime.h>
#include <cuda_fp16.h>
#include <math.h>
#include <stdint.h>

typedef __half fp16;

#define Dc   1024
#define Ec   8
#define Fc   4096
#define NTOK 8192
#define NSLOT (NTOK * 2)
#define MAX_TILES 136
#define NSLOT_PAD (MAX_TILES * 128)   // 17408 padded slots
#define BM 128
#define BN 128
#define BK 32

// blocked operand storage: 8KB block = 128 rows x 32 cols fp16, swizzled
#define BLKB 8192
#define STAGE (2 * BLKB)            // A block + B block = 16384 B
#define NSTG 6
#define NPAIR 3
#define SMEM_DYN (NSTG * STAGE + 256)  // 96KB stages + mbarriers

// ---------------- scratch (device globals) ---------------------------------
__device__ __align__(1024) fp16  g_xg [(size_t)NSLOT_PAD * Dc];   // blocked
__device__ __align__(1024) fp16  g_h  [(size_t)NSLOT_PAD * Fc];   // blocked
__device__ __align__(1024) fp16  g_y  [(size_t)NSLOT_PAD * Dc];   // linear, fp16
__device__ __align__(1024) fp16  g_W1t[(size_t)Ec * Fc * Dc];     // blocked per expert
__device__ __align__(1024) fp16  g_W2t[(size_t)Ec * Dc * Fc];     // blocked per expert
__device__ int   g_perm[NSLOT_PAD];
__device__ int   g_tok_slot[NTOK * 2];
__device__ int   g_tok_e[NTOK * 2];
__device__ float g_tok_w[NTOK * 2];
__device__ int   g_tile_expert[MAX_TILES];
__device__ int   g_ntiles;

// ---------------- helpers ----------------------------------------------------
__device__ __forceinline__ uint32_t smem_u32(const void* p) {
    uint32_t a;
    asm("{ .reg .u64 t; cvta.to.shared.u64 t, %1; cvt.u32.u64 %0, t; }" : "=r"(a) : "l"(p));
    return a;
}
__device__ __forceinline__ uint32_t swz64(uint32_t o) { return o ^ ((o >> 3) & 0x30); }

__device__ __forceinline__ size_t blk_off(int nblkcols, int row, int col) {
    return ((size_t)(row >> 7) * nblkcols + (col >> 5)) * BLKB
         + swz64((uint32_t)((row & 127) << 6) + (uint32_t)((col & 31) << 1));
}

#define MBARRIER_INIT(mb, cnt) asm volatile("mbarrier.init.shared.b64 [%0], %1;" :: "r"(mb), "r"(cnt) : "memory")
#define MBARRIER_EXPECT_TX(mb, tx) asm volatile("mbarrier.arrive.expect_tx.shared.b64 _, [%0], %1;" :: "r"(mb), "r"(tx) : "memory")
#define MBARRIER_WAIT_PARITY(mb, ph) do {                                                   \
    uint32_t _m = (mb), _p = (ph), _d;                                                      \
    asm volatile("{\n\t.reg .pred p;\n\t"                                                   \
        "mbarrier.try_wait.parity.acquire.cta.shared::cta.b64 p, [%1], %2;\n\t"             \
        "selp.b32 %0, 1, 0, p;\n\t}" : "=r"(_d) : "r"(_m), "r"(_p) : "memory");             \
    if (!_d) {                                                                              \
        asm volatile("{\n\t.reg .pred P1;\n\tWL_%=:\n\t"                                    \
            "mbarrier.try_wait.parity.acquire.cta.shared::cta.b64 P1, [%0], %1, 0x989680;\n\t" \
            "@P1 bra.uni WD_%=;\n\tbra.uni WL_%=;\n\tWD_%=:\n\t}"                           \
            :: "r"(_m), "r"(_p) : "memory");                                                \
    }                                                                                       \
} while (0)

__device__ __forceinline__ void bulk_cp(uint32_t sdst, const void* gsrc, uint32_t bytes,
                                        uint32_t mbar) {
    asm volatile(
        "cp.async.bulk.shared::cta.global.mbarrier::complete_tx::bytes [%0], [%1], %2, [%3];"
        :: "r"(sdst), "l"(gsrc), "r"(bytes), "r"(mbar) : "memory");
}

__device__ __forceinline__ void ldmx4(uint32_t addr, uint32_t r[4]) {
    asm volatile("ldmatrix.sync.aligned.m8n8.x4.shared.b16 {%0,%1,%2,%3}, [%4];"
        : "=r"(r[0]), "=r"(r[1]), "=r"(r[2]), "=r"(r[3]) : "r"(addr));
}
__device__ __forceinline__ void mma16816(float c[4], const uint32_t a[4], const uint32_t* b) {
    asm volatile("mma.sync.aligned.m16n8k16.row.col.f32.f16.f16.f32 "
        "{%0,%1,%2,%3}, {%4,%5,%6,%7}, {%8,%9}, {%0,%1,%2,%3};"
        : "+f"(c[0]), "+f"(c[1]), "+f"(c[2]), "+f"(c[3])
        : "r"(a[0]), "r"(a[1]), "r"(a[2]), "r"(a[3]), "r"(b[0]), "r"(b[1]));
}
__device__ __forceinline__ float gelu_exact(float v) {
    return 0.5f * v * (1.0f + erff(v * 0.70710678118654752f));
}
__device__ __forceinline__ uint32_t pack2(fp16 a, fp16 b) {
    return (uint32_t)__half_as_ushort(a) | ((uint32_t)__half_as_ushort(b) << 16);
}

// ---------------- gate (fp32, exact routing) ---------------------------------
__global__ void k_gate(const float* __restrict__ x, const float* __restrict__ Wg,
                       const float* __restrict__ bg) {
    int gtid = blockIdx.x * blockDim.x + threadIdx.x;
    int tok = gtid >> 5, lane = gtid & 31;
    if (tok >= NTOK) return;
    const float* xr = x + (size_t)tok * Dc;
    float acc[Ec];
#pragma unroll
    for (int e = 0; e < Ec; e++) acc[e] = 0.0f;
    for (int d = lane; d < Dc; d += 32) {
        float xv = xr[d];
        const float4* wr = (const float4*)(Wg + (size_t)d * Ec);
        float4 w0 = wr[0], w1 = wr[1];
        acc[0] += xv * w0.x; acc[1] += xv * w0.y; acc[2] += xv * w0.z; acc[3] += xv * w0.w;
        acc[4] += xv * w1.x; acc[5] += xv * w1.y; acc[6] += xv * w1.z; acc[7] += xv * w1.w;
    }
#pragma unroll
    for (int e = 0; e < Ec; e++)
#pragma unroll
        for (int off = 16; off > 0; off >>= 1)
            acc[e] += __shfl_down_sync(0xFFFFFFFFu, acc[e], off);
    if (lane == 0) {
        float v[Ec];
#pragma unroll
        for (int e = 0; e < Ec; e++) v[e] = acc[e] + bg[e];
        int b0 = 0;
#pragma unroll
        for (int e = 1; e < Ec; e++) if (v[e] > v[b0]) b0 = e;
        int b1 = -1; float s = -1e30f;
#pragma unroll
        for (int e = 0; e < Ec; e++) { if (e == b0) continue; if (v[e] > s) { s = v[e]; b1 = e; } }
        float ed = expf(s - v[b0]);
        float p0 = 1.0f / (1.0f + ed);
        float p1 = ed * p0;
        g_tok_e[tok * 2 + 0] = b0; g_tok_e[tok * 2 + 1] = b1;
        g_tok_w[tok * 2 + 0] = p0; g_tok_w[tok * 2 + 1] = p1;
    }
}

// ---------------- scatter: counts, padded prefix, tiles, perm ----------------
__global__ void k_scatter() {
    __shared__ int cnt[Ec], cur[Ec];
    int tid = threadIdx.x;
    for (int s = tid; s < NSLOT_PAD; s += 1024) g_perm[s] = -1;
    if (tid < Ec) cnt[tid] = 0;
    __syncthreads();
    for (int t = tid; t < NTOK; t += 1024) {
        atomicAdd(&cnt[g_tok_e[2 * t]], 1);
        atomicAdd(&cnt[g_tok_e[2 * t + 1]], 1);
    }
    __syncthreads();
    if (tid == 0) {
        int o = 0, nt = 0;
        for (int e = 0; e < Ec; e++) {
            int c = cnt[e];
            cur[e] = o;
            int ntl = (c + 127) >> 7;
            for (int i = 0; i < ntl; i++) g_tile_expert[nt++] = e;
            o += ntl << 7;
        }
        g_ntiles = nt;
    }
    __syncthreads();
    for (int t = tid; t < NTOK; t += 1024) {
#pragma unroll
        for (int k = 0; k < 2; k++) {
            int e = g_tok_e[2 * t + k];
            int pos = atomicAdd(&cur[e], 1);
            g_perm[pos] = t;
            g_tok_slot[2 * t + k] = pos;
        }
    }
}

// ---------------- gather x rows -> blocked swizzled fp16 ----------------------
__global__ void k_gather(const float* __restrict__ x) {
    int s = blockIdx.x;
    int tid = threadIdx.x;
    int d = tid * 4;
    int p = g_perm[s];
    uint2 o2;
    if (p >= 0) {
        float4 v = __ldg((const float4*)(x + (size_t)p * Dc + d));
        o2.x = pack2(__float2half_rn(v.x), __float2half_rn(v.y));
        o2.y = pack2(__float2half_rn(v.z), __float2half_rn(v.w));
    } else {
        o2.x = 0u; o2.y = 0u;
    }
    char* dst = (char*)g_xg + ((size_t)(s >> 7) * (Dc / 32) + (d >> 5)) * BLKB
              + swz64((uint32_t)((s & 127) << 6) + (uint32_t)((d & 31) << 1));
    *(uint2*)dst = o2;
}

// ---------------- weight transpose -> blocked swizzled fp16 -------------------
__global__ void k_tsplit(const float* __restrict__ in, int which, int R, int C) {
    fp16* o = which ? g_W2t : g_W1t;
    __shared__ float t[32][33];
    int e = blockIdx.z;
    int r0 = blockIdx.y * 32, c0 = blockIdx.x * 32;
    int tx = threadIdx.x, ty = threadIdx.y;
    const float* base = in + (size_t)e * R * C;
#pragma unroll
    for (int i = 0; i < 4; i++)
        t[ty + 8 * i][tx] = base[(size_t)(r0 + ty + 8 * i) * C + c0 + tx];
    __syncthreads();
    char* ob = (char*)o + (size_t)e * R * C * 2;
#pragma unroll
    for (int i = 0; i < 4; i++) {
        float v = t[tx][ty + 8 * i];
        int row = c0 + ty + 8 * i;
        int col = r0 + tx;
        *(fp16*)(ob + blk_off(R / 32, row, col)) = __float2half_rn(v);
    }
}

// ---------------- GEMM core: bulk-DMA, paired stages --------------------------
// CTA 128x128x32, 8 warps 4(M) x 2(N), warp tile 32x64. 2 CTAs/SM.
// 6 stages grouped into 3 pairs; one mbarrier + one __syncthreads per 2 chunks.
__device__ __forceinline__ void gemm_core(uint32_t sm0,
        const char* __restrict__ Ab, const char* __restrict__ Bb,
        int NC, int tid, float (&acc)[2][8][4]) {
    const int lane = tid & 31, wid = tid >> 5;
    const int wm = (wid & 3) * 32, wn = (wid >> 2) * 64;
    const uint32_t mb0 = sm0 + NSTG * STAGE;

    const uint32_t aBase = (uint32_t)(wm + (lane & 15)) * 64 + ((lane & 16) ? 16u : 0u);
    const uint32_t bBase = (uint32_t)(wn + (lane & 7) + ((lane & 16) >> 1)) * 64
                           + ((lane & 8) ? 16u : 0u);
    const uint32_t aMask = (aBase >> 3) & 0x30;
    const uint32_t bMask = (bBase >> 3) & 0x30;

#pragma unroll
    for (int mt = 0; mt < 2; mt++)
#pragma unroll
        for (int nt = 0; nt < 8; nt++)
#pragma unroll
            for (int q = 0; q < 4; q++) acc[mt][nt][q] = 0.0f;

    if (tid == 0) {
#pragma unroll
        for (int p = 0; p < NPAIR; p++) MBARRIER_INIT(mb0 + 8 * p, 1);
    }
    __syncthreads();

    // prologue: pairs 0 and 1 in flight (chunks 0..3)
    if (tid == 0) {
#pragma unroll
        for (int p = 0; p < 2; p++) {
            uint32_t mb = mb0 + 8 * p;
            MBARRIER_EXPECT_TX(mb, 2 * STAGE);
#pragma unroll
            for (int c = 0; c < 2; c++) {
                int ch = 2 * p + c;
                uint32_t st = sm0 + (uint32_t)(2 * p + c) * STAGE;
                bulk_cp(st,        Ab + (size_t)ch * BLKB, BLKB, mb);
                bulk_cp(st + BLKB, Bb + (size_t)ch * BLKB, BLKB, mb);
            }
        }
    }

    const int NS = NC >> 1;   // super-iterations (2 chunks each)
    for (int j = 0; j < NS; j++) {
        int pr = j % NPAIR;
        MBARRIER_WAIT_PARITY(mb0 + 8 * pr, (j / NPAIR) & 1);
        if (tid == 0 && j + 2 < NS) {
            int p2 = (j + 2) % NPAIR;
            uint32_t mb = mb0 + 8 * p2;
            MBARRIER_EXPECT_TX(mb, 2 * STAGE);
#pragma unroll
            for (int c = 0; c < 2; c++) {
                int ch = 2 * (j + 2) + c;
                uint32_t st = sm0 + (uint32_t)(2 * p2 + c) * STAGE;
                bulk_cp(st,        Ab + (size_t)ch * BLKB, BLKB, mb);
                bulk_cp(st + BLKB, Bb + (size_t)ch * BLKB, BLKB, mb);
            }
        }
#pragma unroll
        for (int c = 0; c < 2; c++) {
            uint32_t sa = sm0 + (uint32_t)(2 * pr + c) * STAGE;
            uint32_t sb = sa + BLKB;
#pragma unroll
            for (int kk = 0; kk < 2; kk++) {
                const uint32_t kb = kk * 32;
                uint32_t ah[2][4], bh[4][4];
#pragma unroll
                for (int mt = 0; mt < 2; mt++)
                    ldmx4(sa + ((aBase + mt * 1024 + kb) ^ aMask), ah[mt]);
#pragma unroll
                for (int p = 0; p < 4; p++)
                    ldmx4(sb + ((bBase + p * 1024 + kb) ^ bMask), bh[p]);
#pragma unroll
                for (int p = 0; p < 4; p++)
#pragma unroll
                    for (int q = 0; q < 2; q++)
#pragma unroll
                        for (int mt = 0; mt < 2; mt++)
                            mma16816(acc[mt][p * 2 + q], ah[mt], &bh[p][q * 2]);
            }
        }
        __syncthreads();
    }
}

// ---------------- GEMM1: h_blk = fp16(gelu(xg_blk @ W1^T + b1)) ---------------
__global__ void __launch_bounds__(256, 2)
k_mma1(const float* __restrict__ b1) {
    int t = blockIdx.y;
    if (t >= g_ntiles) return;
    const int n0 = blockIdx.x * BN;
    const int e = g_tile_expert[t];

    extern __shared__ char dsm[];
    uint32_t sm0 = (smem_u32(dsm) + 127u) & ~127u;
    int tid = threadIdx.x;

    const char* Ab = (const char*)g_xg + (size_t)t * (Dc / 32) * BLKB;
    const char* Bb = (const char*)g_W1t + (size_t)e * Fc * Dc * 2
                   + (size_t)blockIdx.x * (Dc / 32) * BLKB;

    float acc[2][8][4];
    gemm_core(sm0, Ab, Bb, Dc / BK, tid, acc);

    const int lane = tid & 31, wid = tid >> 5;
    const int wm = (wid & 3) * 32, wn = (wid >> 2) * 64;
    const int rb = wm + (lane >> 2);
    const int cb = wn + (lane & 3) * 2;
    const float* b1e = b1 + (size_t)e * Fc + n0;
    float bv[8][2];
#pragma unroll
    for (int nt = 0; nt < 8; nt++) {
        bv[nt][0] = b1e[cb + nt * 8];
        bv[nt][1] = b1e[cb + nt * 8 + 1];
    }
    char* hb = (char*)g_h + (size_t)t * (Fc / 32) * BLKB;
#pragma unroll
    for (int mt = 0; mt < 2; mt++)
#pragma unroll
        for (int half = 0; half < 2; half++) {
            int r = rb + mt * 16 + half * 8;
#pragma unroll
            for (int nt = 0; nt < 8; nt++) {
                int gc = n0 + cb + nt * 8;
                float v0 = gelu_exact(acc[mt][nt][half * 2 + 0] + bv[nt][0]);
                float v1 = gelu_exact(acc[mt][nt][half * 2 + 1] + bv[nt][1]);
                char* dst = hb + (size_t)(gc >> 5) * BLKB
                          + swz64((uint32_t)(r << 6) + (uint32_t)((gc & 31) << 1));
                *(uint32_t*)dst = pack2(__float2half_rn(v0), __float2half_rn(v1));
            }
        }
}

// ---------------- GEMM2: y[slot] = fp16(h_blk @ W2^T + b2) --------------------
__global__ void __launch_bounds__(256, 2)
k_mma2(const float* __restrict__ b2) {
    int t = blockIdx.y;
    if (t >= g_ntiles) return;
    const int n0 = blockIdx.x * BN;
    const int e = g_tile_expert[t];

    extern __shared__ char dsm[];
    uint32_t sm0 = (smem_u32(dsm) + 127u) & ~127u;
    int tid = threadIdx.x;

    const char* Ab = (const char*)g_h + (size_t)t * (Fc / 32) * BLKB;
    const char* Bb = (const char*)g_W2t + (size_t)e * Dc * Fc * 2
                   + (size_t)blockIdx.x * (Fc / 32) * BLKB;

    float acc[2][8][4];
    gemm_core(sm0, Ab, Bb, Fc / BK, tid, acc);

    const int lane = tid & 31, wid = tid >> 5;
    const int wm = (wid & 3) * 32, wn = (wid >> 2) * 64;
    const int rb = wm + (lane >> 2);
    const int cb = wn + (lane & 3) * 2;
    const float* b2e = b2 + (size_t)e * Dc + n0;
    float bv[8][2];
#pragma unroll
    for (int nt = 0; nt < 8; nt++) {
        bv[nt][0] = b2e[cb + nt * 8];
        bv[nt][1] = b2e[cb + nt * 8 + 1];
    }
#pragma unroll
    for (int mt = 0; mt < 2; mt++)
#pragma unroll
        for (int half = 0; half < 2; half++) {
            int r = rb + mt * 16 + half * 8;
            fp16* yrow = g_y + (size_t)(t * 128 + r) * Dc + n0;
#pragma unroll
            for (int nt = 0; nt < 8; nt++) {
                int c = cb + nt * 8;
                float v0 = acc[mt][nt][half * 2 + 0] + bv[nt][0];
                float v1 = acc[mt][nt][half * 2 + 1] + bv[nt][1];
                *(uint32_t*)(yrow + c) = pack2(__float2half_rn(v0), __float2half_rn(v1));
            }
        }
}

// ---------------- combine: out[t] = w0*y[s0] + w1*y[s1] -----------------------
__global__ void k_combine(float* __restrict__ out) {
    int t = blockIdx.x;
    int tid = threadIdx.x;
    int s0 = g_tok_slot[t * 2 + 0], s1 = g_tok_slot[t * 2 + 1];
    float w0 = g_tok_w[t * 2 + 0],  w1 = g_tok_w[t * 2 + 1];
    const uint2* y0 = (const uint2*)(g_y + (size_t)s0 * Dc);
    const uint2* y1 = (const uint2*)(g_y + (size_t)s1 * Dc);
    uint2 a = __ldg(&y0[tid]);
    uint2 b = __ldg(&y1[tid]);
    __half2 a0 = *(__half2*)&a.x, a1 = *(__half2*)&a.y;
    __half2 b0 = *(__half2*)&b.x, b1 = *(__half2*)&b.y;
    float2 fa0 = __half22float2(a0), fa1 = __half22float2(a1);
    float2 fb0 = __half22float2(b0), fb1 = __half22float2(b1);
    float4 r;
    r.x = w0 * fa0.x + w1 * fb0.x;
    r.y = w0 * fa0.y + w1 * fb0.y;
    r.z = w0 * fa1.x + w1 * fb1.x;
    r.w = w0 * fa1.y + w1 * fb1.y;
    ((float4*)(out + (size_t)t * Dc))[tid] = r;
}

// ---------------- launch (stream fork-join as champion) -----------------------
extern "C" void kernel_launch(void* const* d_in, const int* in_sizes, int n_in,
                              void* d_out, int out_size) {
    const float* x  = (const float*)d_in[0];
    const float* Wg = (const float*)d_in[1];
    const float* bg = (const float*)d_in[2];
    const float* W1 = (const float*)d_in[3];
    const float* b1 = (const float*)d_in[4];
    const float* W2 = (const float*)d_in[5];
    const float* b2 = (const float*)d_in[6];
    float* out = (float*)d_out;

    static cudaStream_t s1 = nullptr, s2 = nullptr;
    static cudaEvent_t e_root = nullptr, e_w1 = nullptr, e_w2 = nullptr;
    static int configured = 0;
    if (!configured) {
        cudaFuncSetAttribute(k_mma1, cudaFuncAttributeMaxDynamicSharedMemorySize, SMEM_DYN);
        cudaFuncSetAttribute(k_mma2, cudaFuncAttributeMaxDynamicSharedMemorySize, SMEM_DYN);
        cudaStreamCreateWithFlags(&s1, cudaStreamNonBlocking);
        cudaStreamCreateWithFlags(&s2, cudaStreamNonBlocking);
        cudaEventCreateWithFlags(&e_root, cudaEventDisableTiming);
        cudaEventCreateWithFlags(&e_w1, cudaEventDisableTiming);
        cudaEventCreateWithFlags(&e_w2, cudaEventDisableTiming);
        configured = 1;
    }

    cudaEventRecord(e_root, 0);
    cudaStreamWaitEvent(s1, e_root, 0);
    cudaStreamWaitEvent(s2, e_root, 0);
    k_tsplit<<<dim3(Fc / 32, Dc / 32, Ec), dim3(32, 8), 0, s1>>>(W1, 0, Dc, Fc);
    cudaEventRecord(e_w1, s1);
    k_tsplit<<<dim3(Dc / 32, Fc / 32, Ec), dim3(32, 8), 0, s2>>>(W2, 1, Fc, Dc);
    cudaEventRecord(e_w2, s2);

    k_gate<<<NTOK / 8, 256>>>(x, Wg, bg);
    k_scatter<<<1, 1024>>>();
    k_gather<<<NSLOT_PAD, 256>>>(x);

    cudaStreamWaitEvent(0, e_w1, 0);
    k_mma1<<<dim3(Fc / BN, MAX_TILES), 256, SMEM_DYN>>>(b1);

    cudaStreamWaitEvent(0, e_w2, 0);
    k_mma2<<<dim3(Dc / BN, MAX_TILES), 256, SMEM_DYN>>>(b2);
    k_combine<<<NTOK, 256>>>(out);
}